// round 8
// baseline (speedup 1.0000x reference)
#include <cuda_runtime.h>
#include <cuda_fp16.h>
#include <cstdint>
#include <cstddef>

// ---------------------------------------------------------------------------
// CrossAttention on sm_100 via mma.sync fp16 (HMMA), split fp32 accum.
// R8: fragment double-buffered inner loop (LDSM latency hidden behind MMAs).
//   S = X(WqWk^T)Y^T + wv ;  out = P·(Y·WvWo) + (bv·Wo+bo)
// ---------------------------------------------------------------------------

#define STAGES 3
#define BK 32
#define TROW 80                     // padded smem row bytes (40 fp16)
#define A_TILE_B (128 * TROW)       // 10240
#define B_TILE_B (256 * TROW)       // 20480

// ---------------- scratch (device globals) ---------------------------------
__device__ __half g_Xh[(size_t)16384*512],  g_Xl[(size_t)16384*512];
__device__ __half g_Yh[(size_t)32768*256],  g_Yl[(size_t)32768*256];
__device__ __half g_Mh[256*512],  g_Ml[256*512];    // (WqWk^T)^T : [256f, 512e]
__device__ __half g_Nh[512*256],  g_Nl[512*256];    // (WvWo)^T   : [512e, 256f]
__device__ __half g_Th[(size_t)16384*256],  g_Tl[(size_t)16384*256];
__device__ __half g_UTh[(size_t)16*512*2048], g_UTl[(size_t)16*512*2048];
__device__ float  g_S[(size_t)16*1024*2048];
__device__ __half g_Ph[(size_t)16384*2048], g_Pl[(size_t)16384*2048];
__device__ float  g_hv[256];       // Wk @ bq
__device__ float  g_wv[32768];     // Y @ (Wk @ bq)  (per-key logit bias)
__device__ float  g_ob[512];       // bv @ Wo + bo

// ---------------- helpers ---------------------------------------------------
__device__ __forceinline__ uint32_t smem_u32(const void* p) {
    uint32_t a;
    asm("{ .reg .u64 t; cvta.to.shared.u64 t, %1; cvt.u32.u64 %0, t; }"
        : "=r"(a) : "l"(p));
    return a;
}
__device__ __forceinline__ void cp16(uint32_t dst, const void* src) {
    asm volatile("cp.async.cg.shared.global [%0], [%1], 16;"
                 :: "r"(dst), "l"(src) : "memory");
}
__device__ __forceinline__ void cp_commit() {
    asm volatile("cp.async.commit_group;" ::: "memory");
}
__device__ __forceinline__ void cp_wait1() {
    asm volatile("cp.async.wait_group 1;" ::: "memory");
}
__device__ __forceinline__ void ldm4(uint32_t* r, uint32_t addr) {
    asm volatile("ldmatrix.sync.aligned.m8n8.x4.shared.b16 {%0,%1,%2,%3}, [%4];"
                 : "=r"(r[0]), "=r"(r[1]), "=r"(r[2]), "=r"(r[3]) : "r"(addr));
}
__device__ __forceinline__ void mma16816(float* d, const uint32_t* a,
                                         uint32_t b0, uint32_t b1) {
    asm volatile(
        "mma.sync.aligned.m16n8k16.row.col.f32.f16.f16.f32 "
        "{%0,%1,%2,%3}, {%4,%5,%6,%7}, {%8,%9}, {%0,%1,%2,%3};"
        : "+f"(d[0]), "+f"(d[1]), "+f"(d[2]), "+f"(d[3])
        : "r"(a[0]), "r"(a[1]), "r"(a[2]), "r"(a[3]), "r"(b0), "r"(b1));
}
__device__ __forceinline__ uint32_t pk2h(__half a, __half b) {
    return ((uint32_t)__half_as_ushort(b) << 16) | (uint32_t)__half_as_ushort(a);
}
__device__ __forceinline__ void split_h(float x, __half& hi, __half& lo) {
    hi = __float2half(x);
    lo = __float2half(x - __half2float(hi));
}

// ---------------------------------------------------------------------------
// Split-fp16 GEMM. A:[Mtot,K], B:[Ntot,K] row-major hi/lo.
// TERMS=3: D = AhBh + AlBh + AhBl.  TERMS=2: D = AhBh + AlBh (B hi only).
// Tile 128x256, BK=32, 3-stage cp.async, 16 warps, double-buffered fragments.
// EPI: 0 = fp32 out, 1 = split-fp16 out. BIAS: 0 none, 1 per-n (z-strided).
// ---------------------------------------------------------------------------
struct GemmArgs {
    const __half *Ah, *Al, *Bh, *Bl;
    const float* bias;
    float* outF;
    __half *outH, *outL;
    int K;
    long long aZ, bZ, outZ;
    int ldc;
    int biasZ;
};

template <int TERMS, int EPI, int BIAS>
__global__ __launch_bounds__(512, 1)
void gemm_mma(GemmArgs g)
{
    constexpr int OFF_AH = 0;
    constexpr int OFF_AL = A_TILE_B;
    constexpr int OFF_BH = 2 * A_TILE_B;
    constexpr int OFF_BL = 2 * A_TILE_B + B_TILE_B;        // TERMS==3 only
    constexpr int STAGE_B = 2 * A_TILE_B + (TERMS == 3 ? 2 : 1) * B_TILE_B;

    extern __shared__ char smem[];
    const uint32_t sm0 = smem_u32(smem);
    const int tid = threadIdx.x, lane = tid & 31, wid = tid >> 5;
    const int wm = wid & 3, wn = wid >> 2;
    const int z = blockIdx.z;
    const int m0 = blockIdx.y * 128, n0 = blockIdx.x * 256;
    const int K = g.K, nkt = K / BK;

    const __half* sAh = g.Ah + (size_t)z * g.aZ + (size_t)m0 * K;
    const __half* sAl = g.Al + (size_t)z * g.aZ + (size_t)m0 * K;
    const __half* sBh = g.Bh + (size_t)z * g.bZ + (size_t)n0 * K;
    const __half* sBl = (TERMS == 3) ? g.Bl + (size_t)z * g.bZ + (size_t)n0 * K : nullptr;
    const float* bp = (BIAS == 1) ? (g.bias + (size_t)z * g.biasZ) : nullptr;

    const int lr = tid >> 2, lc = tid & 3;

    float acc[2][8][4];
#pragma unroll
    for (int i = 0; i < 2; i++)
#pragma unroll
        for (int j = 0; j < 8; j++)
#pragma unroll
            for (int e = 0; e < 4; e++) acc[i][j][e] = 0.0f;

    const uint32_t aoff = (uint32_t)(wm * 32 + (lane & 7) + ((lane >> 3) & 1) * 8) * TROW
                        + (lane >> 4) * 16;
    const uint32_t boff = (uint32_t)(wn * 64 + (lane & 7) + ((lane >> 4) & 1) * 8) * TROW
                        + ((lane >> 3) & 1) * 16;

    auto load_stage = [&](int kt, int s) {
        const uint32_t stb = sm0 + s * STAGE_B;
        const size_t kofs = (size_t)kt * BK;
        const uint32_t drow = (uint32_t)lr * TROW + lc * 16;
        const size_t srow = (size_t)lr * K + kofs + lc * 8;
        cp16(stb + OFF_AH + drow, sAh + srow);
        cp16(stb + OFF_AL + drow, sAl + srow);
#pragma unroll
        for (int h = 0; h < 2; h++) {
            const uint32_t r = lr + h * 128;
            const uint32_t d2 = (uint32_t)r * TROW + lc * 16;
            const size_t s2 = (size_t)r * K + kofs + lc * 8;
            cp16(stb + OFF_BH + d2, sBh + s2);
            if (TERMS == 3) cp16(stb + OFF_BL + d2, sBl + s2);
        }
    };

    // --- double-buffered compute: b1 prefetched behind MMA blocks ---------
    auto compute_stage = [&](int s) {
        const uint32_t stb = sm0 + s * STAGE_B;
        const uint32_t ah_b = stb + OFF_AH + aoff;
        const uint32_t al_b = stb + OFF_AL + aoff;
        const uint32_t bh_b = stb + OFF_BH + boff;
        const uint32_t bl_b = (TERMS == 3) ? stb + OFF_BL + boff : 0;

        uint32_t aH[2][4], aL[2][4], b0[4][4], b1[4][4];
        // ks=0 fragments
#pragma unroll
        for (int mt = 0; mt < 2; mt++) {
            ldm4(aH[mt], ah_b + (uint32_t)mt * 16 * TROW);
            ldm4(aL[mt], al_b + (uint32_t)mt * 16 * TROW);
        }
#pragma unroll
        for (int np = 0; np < 4; np++)
            ldm4(b0[np], bh_b + (uint32_t)np * 16 * TROW);

        if (TERMS == 3) {
#pragma unroll
            for (int ks = 0; ks < 2; ks++) {
                const uint32_t ko = ks * 32;
                // prefetch Bl(ks) into b1 — hidden behind 32 MMAs below
#pragma unroll
                for (int np = 0; np < 4; np++)
                    ldm4(b1[np], bl_b + (uint32_t)np * 16 * TROW + ko);
                // Ah @ Bh
#pragma unroll
                for (int mt = 0; mt < 2; mt++)
#pragma unroll
                    for (int nt = 0; nt < 8; nt++) {
                        const uint32_t* b = &b0[nt >> 1][(nt & 1) * 2];
                        mma16816(acc[mt][nt], aH[mt], b[0], b[1]);
                    }
                // Al @ Bh
#pragma unroll
                for (int mt = 0; mt < 2; mt++)
#pragma unroll
                    for (int nt = 0; nt < 8; nt++) {
                        const uint32_t* b = &b0[nt >> 1][(nt & 1) * 2];
                        mma16816(acc[mt][nt], aL[mt], b[0], b[1]);
                    }
                // b0 free -> prefetch Bh(ks+1), hidden behind AhBl MMAs
                if (ks == 0)
#pragma unroll
                    for (int np = 0; np < 4; np++)
                        ldm4(b0[np], bh_b + (uint32_t)np * 16 * TROW + 32);
                // Ah @ Bl
#pragma unroll
                for (int mt = 0; mt < 2; mt++)
#pragma unroll
                    for (int nt = 0; nt < 8; nt++) {
                        const uint32_t* b = &b1[nt >> 1][(nt & 1) * 2];
                        mma16816(acc[mt][nt], aH[mt], b[0], b[1]);
                    }
                // aH/aL free -> fragments for ks+1
                if (ks == 0)
#pragma unroll
                    for (int mt = 0; mt < 2; mt++) {
                        ldm4(aH[mt], ah_b + (uint32_t)mt * 16 * TROW + 32);
                        ldm4(aL[mt], al_b + (uint32_t)mt * 16 * TROW + 32);
                    }
            }
        } else {
            // TERMS == 2: ping-pong b0/b1 across ks
#pragma unroll
            for (int np = 0; np < 4; np++)
                ldm4(b1[np], bh_b + (uint32_t)np * 16 * TROW + 32);    // Bh(ks1)
#pragma unroll
            for (int ks = 0; ks < 2; ks++) {
                uint32_t (*bb)[4] = (ks == 0) ? b0 : b1;
#pragma unroll
                for (int mt = 0; mt < 2; mt++)
#pragma unroll
                    for (int nt = 0; nt < 8; nt++) {
                        const uint32_t* b = &bb[nt >> 1][(nt & 1) * 2];
                        mma16816(acc[mt][nt], aH[mt], b[0], b[1]);
                    }
#pragma unroll
                for (int mt = 0; mt < 2; mt++)
#pragma unroll
                    for (int nt = 0; nt < 8; nt++) {
                        const uint32_t* b = &bb[nt >> 1][(nt & 1) * 2];
                        mma16816(acc[mt][nt], aL[mt], b[0], b[1]);
                    }
                if (ks == 0)
#pragma unroll
                    for (int mt = 0; mt < 2; mt++) {
                        ldm4(aH[mt], ah_b + (uint32_t)mt * 16 * TROW + 32);
                        ldm4(aL[mt], al_b + (uint32_t)mt * 16 * TROW + 32);
                    }
            }
        }
    };

#pragma unroll
    for (int s = 0; s < STAGES - 1; s++) { load_stage(s, s); cp_commit(); }
    for (int kt = 0; kt < nkt; kt++) {
        cp_wait1();
        __syncthreads();
        const int nx = kt + STAGES - 1;
        if (nx < nkt) load_stage(nx, nx % STAGES);
        cp_commit();
        compute_stage(kt % STAGES);
    }

    // ---------------- epilogue --------------------------------------------
    const int rr = lane >> 2, rc = (lane & 3) * 2;
#pragma unroll
    for (int mt = 0; mt < 2; mt++) {
#pragma unroll
        for (int nt = 0; nt < 8; nt++) {
            float* d = acc[mt][nt];
            const int m = m0 + wm * 32 + mt * 16 + rr;
            const int n = n0 + wn * 64 + nt * 8 + rc;
            float v[4] = {d[0], d[1], d[2], d[3]};
            if (BIAS == 1) {
                const float b0v = bp[n], b1v = bp[n + 1];
                v[0] += b0v; v[1] += b1v; v[2] += b0v; v[3] += b1v;
            }
            if (EPI == 0) {
                float* o = g.outF + (size_t)z * g.outZ;
                *(float2*)&o[(size_t)m * g.ldc + n]       = make_float2(v[0], v[1]);
                *(float2*)&o[(size_t)(m + 8) * g.ldc + n] = make_float2(v[2], v[3]);
            } else {
                __half hi[4], lo[4];
#pragma unroll
                for (int e = 0; e < 4; e++) split_h(v[e], hi[e], lo[e]);
                __half* oh = g.outH + (size_t)z * g.outZ;
                __half* ol = g.outL + (size_t)z * g.outZ;
                *(uint32_t*)&oh[(size_t)m * g.ldc + n]       = pk2h(hi[0], hi[1]);
                *(uint32_t*)&oh[(size_t)(m + 8) * g.ldc + n] = pk2h(hi[2], hi[3]);
                *(uint32_t*)&ol[(size_t)m * g.ldc + n]       = pk2h(lo[0], lo[1]);
                *(uint32_t*)&ol[(size_t)(m + 8) * g.ldc + n] = pk2h(lo[2], lo[3]);
            }
        }
    }
}

// ---------------------------------------------------------------------------
// fp32 row-major -> hi/lo fp16 row-major
// ---------------------------------------------------------------------------
__global__ __launch_bounds__(256)
void split_rm(const float* __restrict__ in, __half* __restrict__ h,
              __half* __restrict__ l, size_t n8)
{
    const size_t id = (size_t)blockIdx.x * blockDim.x + threadIdx.x;
    if (id >= n8) return;
    float v[8];
    *(float4*)&v[0] = ((const float4*)in)[id * 2];
    *(float4*)&v[4] = ((const float4*)in)[id * 2 + 1];
    __half hi[8], lo[8];
#pragma unroll
    for (int e = 0; e < 8; e++) split_h(v[e], hi[e], lo[e]);
    uint4 hv, lv;
    hv.x = pk2h(hi[0],hi[1]); hv.y = pk2h(hi[2],hi[3]); hv.z = pk2h(hi[4],hi[5]); hv.w = pk2h(hi[6],hi[7]);
    lv.x = pk2h(lo[0],lo[1]); lv.y = pk2h(lo[2],lo[3]); lv.z = pk2h(lo[4],lo[5]); lv.w = pk2h(lo[6],lo[7]);
    *(uint4*)&h[id * 8] = hv;
    *(uint4*)&l[id * 8] = lv;
}

// M^T[f,e] = sum_a Wq[e,a] * Wk[f,a]  -> fp16 split, layout [f*512+e]
__global__ __launch_bounds__(256)
void prep_MT(const float* __restrict__ Wq, const float* __restrict__ Wk,
             __half* __restrict__ h, __half* __restrict__ l)
{
    __shared__ float krow[512];
    const int f = blockIdx.x;
    for (int a = threadIdx.x; a < 512; a += 256) krow[a] = Wk[(size_t)f * 512 + a];
    __syncthreads();
    for (int e = threadIdx.x; e < 512; e += 256) {
        const float* qrow = Wq + (size_t)e * 512;
        float s = 0.0f;
#pragma unroll 4
        for (int a = 0; a < 512; a += 4) {
            const float4 q4 = *(const float4*)&qrow[a];
            s = fmaf(q4.x, krow[a], s);
            s = fmaf(q4.y, krow[a+1], s);
            s = fmaf(q4.z, krow[a+2], s);
            s = fmaf(q4.w, krow[a+3], s);
        }
        __half hi, lo; split_h(s, hi, lo);
        h[(size_t)f * 512 + e] = hi;
        l[(size_t)f * 512 + e] = lo;
    }
}

// N^T[e,f] = sum_a Wv[f,a] * Wo[a,e] -> fp16 split, layout [e*256+f]
__global__ __launch_bounds__(512)
void prep_NT(const float* __restrict__ Wv, const float* __restrict__ Wo,
             __half* __restrict__ h, __half* __restrict__ l)
{
    __shared__ float vrow[512];
    const int f = blockIdx.x;
    if (threadIdx.x < 512) vrow[threadIdx.x] = Wv[(size_t)f * 512 + threadIdx.x];
    __syncthreads();
    const int e = threadIdx.x;
    float s = 0.0f;
#pragma unroll 8
    for (int a = 0; a < 512; a++) s = fmaf(vrow[a], __ldg(&Wo[(size_t)a * 512 + e]), s);
    __half hi, lo; split_h(s, hi, lo);
    h[(size_t)e * 256 + f] = hi;
    l[(size_t)e * 256 + f] = lo;
}

// hv[f] = Wk[f,:] . bq
__global__ __launch_bounds__(256)
void prep_hv(const float* __restrict__ Wk, const float* __restrict__ bq,
             float* __restrict__ hv)
{
    const int f = threadIdx.x;
    float s = 0.0f;
    for (int a = 0; a < 512; a++) s = fmaf(Wk[(size_t)f * 512 + a], bq[a], s);
    hv[f] = s;
}

// wv[r] = Y[r,:] . hv
__global__ __launch_bounds__(256)
void prep_wv(const float* __restrict__ Y, const float* __restrict__ hv,
             float* __restrict__ wv)
{
    __shared__ float hs[256];
    if (threadIdx.x < 256) hs[threadIdx.x] = hv[threadIdx.x];
    __syncthreads();
    const int lane = threadIdx.x & 31;
    const int w = threadIdx.x >> 5;
    const size_t r = (size_t)blockIdx.x * 8 + w;
    const float* row = Y + r * 256;
    float s = 0.0f;
#pragma unroll
    for (int j = 0; j < 8; j++) s = fmaf(row[lane * 8 + j], hs[lane * 8 + j], s);
#pragma unroll
    for (int o = 16; o; o >>= 1) s += __shfl_xor_sync(0xffffffffu, s, o);
    if (lane == 0) wv[r] = s;
}

// ob[e] = bo[e] + bv . Wo[:,e]
__global__ __launch_bounds__(512)
void prep_ob(const float* __restrict__ bv, const float* __restrict__ Wo,
             const float* __restrict__ bo, float* __restrict__ ob)
{
    const int e = threadIdx.x;
    float s = bo[e];
    for (int a = 0; a < 512; a++) s = fmaf(bv[a], Wo[(size_t)a * 512 + e], s);
    ob[e] = s;
}

// ---------------------------------------------------------------------------
// Softmax over 2048-col fp32 rows -> hi/lo fp16 row-major
// ---------------------------------------------------------------------------
__global__ __launch_bounds__(256)
void softmax_split(const float* __restrict__ S, __half* __restrict__ Sh,
                   __half* __restrict__ Sl)
{
    const size_t r = blockIdx.x;
    const float* row = S + r * 2048;
    const int tid = threadIdx.x;
    const int c0 = tid * 8;

    float v[8];
    *(float4*)&v[0] = *(const float4*)&row[c0];
    *(float4*)&v[4] = *(const float4*)&row[c0 + 4];

    __shared__ float red[8];
    float m = v[0];
#pragma unroll
    for (int e = 1; e < 8; e++) m = fmaxf(m, v[e]);
#pragma unroll
    for (int o = 16; o; o >>= 1) m = fmaxf(m, __shfl_xor_sync(0xffffffffu, m, o));
    if ((tid & 31) == 0) red[tid >> 5] = m;
    __syncthreads();
    float mx = red[0];
#pragma unroll
    for (int i = 1; i < 8; i++) mx = fmaxf(mx, red[i]);
    __syncthreads();

    float s = 0.0f;
#pragma unroll
    for (int e = 0; e < 8; e++) { v[e] = __expf(v[e] - mx); s += v[e]; }
#pragma unroll
    for (int o = 16; o; o >>= 1) s += __shfl_xor_sync(0xffffffffu, s, o);
    if ((tid & 31) == 0) red[tid >> 5] = s;
    __syncthreads();
    float st = 0.0f;
#pragma unroll
    for (int i = 0; i < 8; i++) st += red[i];
    const float inv = 1.0f / st;

    __half hi[8], lo[8];
#pragma unroll
    for (int e = 0; e < 8; e++) split_h(v[e] * inv, hi[e], lo[e]);
    uint4 hv, lv;
    hv.x = pk2h(hi[0],hi[1]); hv.y = pk2h(hi[2],hi[3]); hv.z = pk2h(hi[4],hi[5]); hv.w = pk2h(hi[6],hi[7]);
    lv.x = pk2h(lo[0],lo[1]); lv.y = pk2h(lo[2],lo[3]); lv.z = pk2h(lo[4],lo[5]); lv.w = pk2h(lo[6],lo[7]);
    *(uint4*)&Sh[r * 2048 + c0] = hv;
    *(uint4*)&Sl[r * 2048 + c0] = lv;
}

// ---------------------------------------------------------------------------
// Launch
// ---------------------------------------------------------------------------
extern "C" void kernel_launch(void* const* d_in, const int* in_sizes, int n_in,
                              void* d_out, int out_size)
{
    const float* X  = (const float*)d_in[0];
    const float* Y  = (const float*)d_in[1];
    const float* Wq = (const float*)d_in[2];
    const float* bq = (const float*)d_in[3];
    const float* Wk = (const float*)d_in[4];
    const float* Wv = (const float*)d_in[6];
    const float* bv = (const float*)d_in[7];
    const float* Wo = (const float*)d_in[8];
    const float* bo = (const float*)d_in[9];
    float* out = (float*)d_out;

    constexpr int SMEM3 = STAGES * (2 * A_TILE_B + 2 * B_TILE_B);   // 184320
    constexpr int SMEM2 = STAGES * (2 * A_TILE_B + 1 * B_TILE_B);   // 122880
    cudaFuncSetAttribute(gemm_mma<3,0,1>, cudaFuncAttributeMaxDynamicSharedMemorySize, SMEM3);
    cudaFuncSetAttribute(gemm_mma<3,1,0>, cudaFuncAttributeMaxDynamicSharedMemorySize, SMEM3);
    cudaFuncSetAttribute(gemm_mma<2,0,1>, cudaFuncAttributeMaxDynamicSharedMemorySize, SMEM2);

    __half *Xh,*Xl,*Yh,*Yl,*Mh,*Ml,*Nh,*Nl,*Th,*Tl,*UTh,*UTl,*Ph,*Pl;
    float *S,*hv,*wv,*ob;
    cudaGetSymbolAddress((void**)&Xh, g_Xh);   cudaGetSymbolAddress((void**)&Xl, g_Xl);
    cudaGetSymbolAddress((void**)&Yh, g_Yh);   cudaGetSymbolAddress((void**)&Yl, g_Yl);
    cudaGetSymbolAddress((void**)&Mh, g_Mh);   cudaGetSymbolAddress((void**)&Ml, g_Ml);
    cudaGetSymbolAddress((void**)&Nh, g_Nh);   cudaGetSymbolAddress((void**)&Nl, g_Nl);
    cudaGetSymbolAddress((void**)&Th, g_Th);   cudaGetSymbolAddress((void**)&Tl, g_Tl);
    cudaGetSymbolAddress((void**)&UTh, g_UTh); cudaGetSymbolAddress((void**)&UTl, g_UTl);
    cudaGetSymbolAddress((void**)&Ph, g_Ph);   cudaGetSymbolAddress((void**)&Pl, g_Pl);
    cudaGetSymbolAddress((void**)&S, g_S);
    cudaGetSymbolAddress((void**)&hv, g_hv);
    cudaGetSymbolAddress((void**)&wv, g_wv);
    cudaGetSymbolAddress((void**)&ob, g_ob);

    // 1,2: input splits
    split_rm<<<4096, 256>>>(X, Xh, Xl, (size_t)16384*512/8);
    split_rm<<<4096, 256>>>(Y, Yh, Yl, (size_t)32768*256/8);
    // 3: M^T
    prep_MT<<<256, 256>>>(Wq, Wk, Mh, Ml);
    // 4: T = X @ M -> split [16384,256]   (ncu capture slot)
    {
        GemmArgs a{Xh, Xl, Mh, Ml, nullptr, nullptr, Th, Tl,
                   512, 0, 0, 0, 256, 0};
        gemm_mma<3,1,0><<<dim3(1,128,1), 512, SMEM3>>>(a);
    }
    // 5,6: logit key-bias
    prep_hv<<<1, 256>>>(Wk, bq, hv);
    prep_wv<<<4096, 256>>>(Y, hv, wv);
    // 7: S = T_z @ Y_z^T + wv -> fp32 [1024,2048] x16
    {
        GemmArgs a{Th, Tl, Yh, Yl, wv, S, nullptr, nullptr,
                   256, (long long)1024*256, (long long)2048*256,
                   (long long)1024*2048, 2048, 2048};
        gemm_mma<3,0,1><<<dim3(8,8,16), 512, SMEM3>>>(a);
    }
    // 8: softmax -> P split
    softmax_split<<<16384, 256>>>(S, Ph, Pl);
    // 9: N^T
    prep_NT<<<256, 512>>>(Wv, Wo, Nh, Nl);
    // 10: U^T = N^T @ Y_z^T -> split [512,2048] x16
    {
        GemmArgs a{Nh, Nl, Yh, Yl, nullptr, nullptr, UTh, UTl,
                   256, 0, (long long)2048*256, (long long)512*2048, 2048, 0};
        gemm_mma<3,1,0><<<dim3(8,4,16), 512, SMEM3>>>(a);
    }
    // 11: output bias
    prep_ob<<<1, 512>>>(bv, Wo, bo, ob);
    // 12: out = (Ph+Pl) @ Uh + ob -> fp32 [1024,512] x16   (2-term)
    {
        GemmArgs a{Ph, Pl, UTh, nullptr, ob, out, nullptr, nullptr,
                   2048, (long long)1024*2048, (long long)512*2048,
                   (long long)1024*512, 512, 0};
        gemm_mma<2,0,1><<<dim3(2,8,16), 512, SMEM2>>>(a);
    }
}

// round 9
// speedup vs baseline: 1.2195x; 1.2195x over previous
#include <cuda_runtime.h>
#include <cuda_fp16.h>
#include <cstdint>
#include <cstddef>

// ---------------------------------------------------------------------------
// CrossAttention on sm_100 via mma.sync fp16 (HMMA), split fp32 accum.
// R9: re-associated output chain:  C = P@Y (2-term), out = C@(WvWo) (3-term).
// Deletes the U^T GEMM. Engine = R7 inner loop (best measured).
//   S = X(WqWk^T)Y^T + wv ;  out = (P@Y)@(WvWo) + (bv·Wo+bo)
// ---------------------------------------------------------------------------

#define STAGES 3
#define BK 32
#define TROW 80                     // padded smem row bytes (40 fp16)
#define A_TILE_B (128 * TROW)       // 10240
#define B_TILE_B (256 * TROW)       // 20480

// ---------------- scratch (device globals) ---------------------------------
__device__ __half g_Xh[(size_t)16384*512],  g_Xl[(size_t)16384*512];
__device__ __half g_Yh[(size_t)32768*256],  g_Yl[(size_t)32768*256];
__device__ __half g_YTh[(size_t)16*256*2048], g_YTl[(size_t)16*256*2048];
__device__ __half g_Mh[256*512],  g_Ml[256*512];    // (WqWk^T)^T : [256f, 512e]
__device__ __half g_Nh[512*256],  g_Nl[512*256];    // (WvWo)^T   : [512e, 256f]
__device__ __half g_Th[(size_t)16384*256],  g_Tl[(size_t)16384*256];
__device__ float  g_S[(size_t)16*1024*2048];
__device__ __half g_Ph[(size_t)16384*2048], g_Pl[(size_t)16384*2048];
__device__ __half g_Ch[(size_t)16384*256],  g_Cl[(size_t)16384*256];
__device__ float  g_hv[256];       // Wk @ bq
__device__ float  g_wv[32768];     // Y @ (Wk @ bq)  (per-key logit bias)
__device__ float  g_ob[512];       // bv @ Wo + bo

// ---------------- helpers ---------------------------------------------------
__device__ __forceinline__ uint32_t smem_u32(const void* p) {
    uint32_t a;
    asm("{ .reg .u64 t; cvta.to.shared.u64 t, %1; cvt.u32.u64 %0, t; }"
        : "=r"(a) : "l"(p));
    return a;
}
__device__ __forceinline__ void cp16(uint32_t dst, const void* src) {
    asm volatile("cp.async.cg.shared.global [%0], [%1], 16;"
                 :: "r"(dst), "l"(src) : "memory");
}
__device__ __forceinline__ void cp_commit() {
    asm volatile("cp.async.commit_group;" ::: "memory");
}
__device__ __forceinline__ void cp_wait1() {
    asm volatile("cp.async.wait_group 1;" ::: "memory");
}
__device__ __forceinline__ void ldm4(uint32_t* r, uint32_t addr) {
    asm volatile("ldmatrix.sync.aligned.m8n8.x4.shared.b16 {%0,%1,%2,%3}, [%4];"
                 : "=r"(r[0]), "=r"(r[1]), "=r"(r[2]), "=r"(r[3]) : "r"(addr));
}
__device__ __forceinline__ void mma16816(float* d, const uint32_t* a,
                                         uint32_t b0, uint32_t b1) {
    asm volatile(
        "mma.sync.aligned.m16n8k16.row.col.f32.f16.f16.f32 "
        "{%0,%1,%2,%3}, {%4,%5,%6,%7}, {%8,%9}, {%0,%1,%2,%3};"
        : "+f"(d[0]), "+f"(d[1]), "+f"(d[2]), "+f"(d[3])
        : "r"(a[0]), "r"(a[1]), "r"(a[2]), "r"(a[3]), "r"(b0), "r"(b1));
}
__device__ __forceinline__ uint32_t pk2h(__half a, __half b) {
    return ((uint32_t)__half_as_ushort(b) << 16) | (uint32_t)__half_as_ushort(a);
}
__device__ __forceinline__ void split_h(float x, __half& hi, __half& lo) {
    hi = __float2half(x);
    lo = __float2half(x - __half2float(hi));
}

// ---------------------------------------------------------------------------
// Split-fp16 GEMM. A:[Mtot,K], B:[Ntot,K] row-major hi/lo.
// TERMS=3: D = AhBh + AlBh + AhBl.  TERMS=2: D = AhBh + AlBh (B hi only).
// Tile 128x256, BK=32, 3-stage cp.async, 16 warps (4Mx4N).
// EPI: 0 = fp32 out, 1 = split-fp16 out. BIAS: 0 none, 1 per-n (z-strided).
// ---------------------------------------------------------------------------
struct GemmArgs {
    const __half *Ah, *Al, *Bh, *Bl;
    const float* bias;
    float* outF;
    __half *outH, *outL;
    int K;
    long long aZ, bZ, outZ;
    int ldc;
    int biasZ;
};

template <int TERMS, int EPI, int BIAS>
__global__ __launch_bounds__(512, 1)
void gemm_mma(GemmArgs g)
{
    constexpr int OFF_AH = 0;
    constexpr int OFF_AL = A_TILE_B;
    constexpr int OFF_BH = 2 * A_TILE_B;
    constexpr int OFF_BL = 2 * A_TILE_B + B_TILE_B;        // TERMS==3 only
    constexpr int STAGE_B = 2 * A_TILE_B + (TERMS == 3 ? 2 : 1) * B_TILE_B;

    extern __shared__ char smem[];
    const uint32_t sm0 = smem_u32(smem);
    const int tid = threadIdx.x, lane = tid & 31, wid = tid >> 5;
    const int wm = wid & 3, wn = wid >> 2;
    const int z = blockIdx.z;
    const int m0 = blockIdx.y * 128, n0 = blockIdx.x * 256;
    const int K = g.K, nkt = K / BK;

    const __half* sAh = g.Ah + (size_t)z * g.aZ + (size_t)m0 * K;
    const __half* sAl = g.Al + (size_t)z * g.aZ + (size_t)m0 * K;
    const __half* sBh = g.Bh + (size_t)z * g.bZ + (size_t)n0 * K;
    const __half* sBl = (TERMS == 3) ? g.Bl + (size_t)z * g.bZ + (size_t)n0 * K : nullptr;
    const float* bp = (BIAS == 1) ? (g.bias + (size_t)z * g.biasZ) : nullptr;

    const int lr = tid >> 2, lc = tid & 3;

    float acc[2][8][4];
#pragma unroll
    for (int i = 0; i < 2; i++)
#pragma unroll
        for (int j = 0; j < 8; j++)
#pragma unroll
            for (int e = 0; e < 4; e++) acc[i][j][e] = 0.0f;

    const uint32_t aoff = (uint32_t)(wm * 32 + (lane & 7) + ((lane >> 3) & 1) * 8) * TROW
                        + (lane >> 4) * 16;
    const uint32_t boff = (uint32_t)(wn * 64 + (lane & 7) + ((lane >> 4) & 1) * 8) * TROW
                        + ((lane >> 3) & 1) * 16;

    auto load_stage = [&](int kt, int s) {
        const uint32_t stb = sm0 + s * STAGE_B;
        const size_t kofs = (size_t)kt * BK;
        const uint32_t drow = (uint32_t)lr * TROW + lc * 16;
        const size_t srow = (size_t)lr * K + kofs + lc * 8;
        cp16(stb + OFF_AH + drow, sAh + srow);
        cp16(stb + OFF_AL + drow, sAl + srow);
#pragma unroll
        for (int h = 0; h < 2; h++) {
            const uint32_t r = lr + h * 128;
            const uint32_t d2 = (uint32_t)r * TROW + lc * 16;
            const size_t s2 = (size_t)r * K + kofs + lc * 8;
            cp16(stb + OFF_BH + d2, sBh + s2);
            if (TERMS == 3) cp16(stb + OFF_BL + d2, sBl + s2);
        }
    };

    auto compute_stage = [&](int s) {
        const uint32_t stb = sm0 + s * STAGE_B;
#pragma unroll
        for (int ks = 0; ks < 2; ks++) {
            uint32_t aH[2][4], aL[2][4], bB[4][4];
#pragma unroll
            for (int mt = 0; mt < 2; mt++) {
                const uint32_t o = aoff + (uint32_t)mt * 16 * TROW + ks * 32;
                ldm4(aH[mt], stb + OFF_AH + o);
                ldm4(aL[mt], stb + OFF_AL + o);
            }
#pragma unroll
            for (int np = 0; np < 4; np++)
                ldm4(bB[np], stb + OFF_BH + boff + (uint32_t)np * 16 * TROW + ks * 32);
            // Ah @ Bh
#pragma unroll
            for (int mt = 0; mt < 2; mt++)
#pragma unroll
                for (int nt = 0; nt < 8; nt++) {
                    const uint32_t* b = &bB[nt >> 1][(nt & 1) * 2];
                    mma16816(acc[mt][nt], aH[mt], b[0], b[1]);
                }
            // Al @ Bh
#pragma unroll
            for (int mt = 0; mt < 2; mt++)
#pragma unroll
                for (int nt = 0; nt < 8; nt++) {
                    const uint32_t* b = &bB[nt >> 1][(nt & 1) * 2];
                    mma16816(acc[mt][nt], aL[mt], b[0], b[1]);
                }
            if (TERMS == 3) {
                // reload same regs with Bl, then Ah @ Bl
#pragma unroll
                for (int np = 0; np < 4; np++)
                    ldm4(bB[np], stb + OFF_BL + boff + (uint32_t)np * 16 * TROW + ks * 32);
#pragma unroll
                for (int mt = 0; mt < 2; mt++)
#pragma unroll
                    for (int nt = 0; nt < 8; nt++) {
                        const uint32_t* b = &bB[nt >> 1][(nt & 1) * 2];
                        mma16816(acc[mt][nt], aH[mt], b[0], b[1]);
                    }
            }
        }
    };

#pragma unroll
    for (int s = 0; s < STAGES - 1; s++) { load_stage(s, s); cp_commit(); }
    for (int kt = 0; kt < nkt; kt++) {
        cp_wait1();
        __syncthreads();
        const int nx = kt + STAGES - 1;
        if (nx < nkt) load_stage(nx, nx % STAGES);
        cp_commit();
        compute_stage(kt % STAGES);
    }

    // ---------------- epilogue --------------------------------------------
    const int rr = lane >> 2, rc = (lane & 3) * 2;
#pragma unroll
    for (int mt = 0; mt < 2; mt++) {
#pragma unroll
        for (int nt = 0; nt < 8; nt++) {
            float* d = acc[mt][nt];
            const int m = m0 + wm * 32 + mt * 16 + rr;
            const int n = n0 + wn * 64 + nt * 8 + rc;
            float v[4] = {d[0], d[1], d[2], d[3]};
            if (BIAS == 1) {
                const float b0v = bp[n], b1v = bp[n + 1];
                v[0] += b0v; v[1] += b1v; v[2] += b0v; v[3] += b1v;
            }
            if (EPI == 0) {
                float* o = g.outF + (size_t)z * g.outZ;
                *(float2*)&o[(size_t)m * g.ldc + n]       = make_float2(v[0], v[1]);
                *(float2*)&o[(size_t)(m + 8) * g.ldc + n] = make_float2(v[2], v[3]);
            } else {
                __half hi[4], lo[4];
#pragma unroll
                for (int e = 0; e < 4; e++) split_h(v[e], hi[e], lo[e]);
                __half* oh = g.outH + (size_t)z * g.outZ;
                __half* ol = g.outL + (size_t)z * g.outZ;
                *(uint32_t*)&oh[(size_t)m * g.ldc + n]       = pk2h(hi[0], hi[1]);
                *(uint32_t*)&oh[(size_t)(m + 8) * g.ldc + n] = pk2h(hi[2], hi[3]);
                *(uint32_t*)&ol[(size_t)m * g.ldc + n]       = pk2h(lo[0], lo[1]);
                *(uint32_t*)&ol[(size_t)(m + 8) * g.ldc + n] = pk2h(lo[2], lo[3]);
            }
        }
    }
}

// ---------------------------------------------------------------------------
// fp32 row-major -> hi/lo fp16 row-major
// ---------------------------------------------------------------------------
__global__ __launch_bounds__(256)
void split_rm(const float* __restrict__ in, __half* __restrict__ h,
              __half* __restrict__ l, size_t n8)
{
    const size_t id = (size_t)blockIdx.x * blockDim.x + threadIdx.x;
    if (id >= n8) return;
    float v[8];
    *(float4*)&v[0] = ((const float4*)in)[id * 2];
    *(float4*)&v[4] = ((const float4*)in)[id * 2 + 1];
    __half hi[8], lo[8];
#pragma unroll
    for (int e = 0; e < 8; e++) split_h(v[e], hi[e], lo[e]);
    uint4 hv, lv;
    hv.x = pk2h(hi[0],hi[1]); hv.y = pk2h(hi[2],hi[3]); hv.z = pk2h(hi[4],hi[5]); hv.w = pk2h(hi[6],hi[7]);
    lv.x = pk2h(lo[0],lo[1]); lv.y = pk2h(lo[2],lo[3]); lv.z = pk2h(lo[4],lo[5]); lv.w = pk2h(lo[6],lo[7]);
    *(uint4*)&h[id * 8] = hv;
    *(uint4*)&l[id * 8] = lv;
}

// ---------------------------------------------------------------------------
// Y [2048,256] fp32 per batch -> Y^T split fp16 [256,2048] per batch.
// 64x64 tiles via smem.
// ---------------------------------------------------------------------------
__global__ __launch_bounds__(256)
void transpose_split(const float* __restrict__ Y, __half* __restrict__ th,
                     __half* __restrict__ tl)
{
    __shared__ float t[64][65];
    const int z = blockIdx.z;
    const int k0 = blockIdx.x * 64;     // key offset
    const int f0 = blockIdx.y * 64;     // feature offset
    const float* Yb = Y + (size_t)z * 2048 * 256;
    const int tid = threadIdx.x;

    for (int i = tid; i < 64 * 16; i += 256) {
        const int r = i >> 4, c4 = i & 15;
        const float4 v = *(const float4*)&Yb[(size_t)(k0 + r) * 256 + f0 + c4 * 4];
        t[r][c4 * 4 + 0] = v.x; t[r][c4 * 4 + 1] = v.y;
        t[r][c4 * 4 + 2] = v.z; t[r][c4 * 4 + 3] = v.w;
    }
    __syncthreads();

    __half* thb = th + (size_t)z * 256 * 2048;
    __half* tlb = tl + (size_t)z * 256 * 2048;
    for (int i = tid; i < 64 * 16; i += 256) {
        const int f = i >> 4, c4 = i & 15;
        __half hi[4], lo[4];
#pragma unroll
        for (int e = 0; e < 4; e++) split_h(t[c4 * 4 + e][f], hi[e], lo[e]);
        uint2 hv, lv;
        hv.x = pk2h(hi[0], hi[1]); hv.y = pk2h(hi[2], hi[3]);
        lv.x = pk2h(lo[0], lo[1]); lv.y = pk2h(lo[2], lo[3]);
        *(uint2*)&thb[(size_t)(f0 + f) * 2048 + k0 + c4 * 4] = hv;
        *(uint2*)&tlb[(size_t)(f0 + f) * 2048 + k0 + c4 * 4] = lv;
    }
}

// M^T[f,e] = sum_a Wq[e,a] * Wk[f,a]  -> fp16 split, layout [f*512+e]
__global__ __launch_bounds__(256)
void prep_MT(const float* __restrict__ Wq, const float* __restrict__ Wk,
             __half* __restrict__ h, __half* __restrict__ l)
{
    __shared__ float krow[512];
    const int f = blockIdx.x;
    for (int a = threadIdx.x; a < 512; a += 256) krow[a] = Wk[(size_t)f * 512 + a];
    __syncthreads();
    for (int e = threadIdx.x; e < 512; e += 256) {
        const float* qrow = Wq + (size_t)e * 512;
        float s = 0.0f;
#pragma unroll 4
        for (int a = 0; a < 512; a += 4) {
            const float4 q4 = *(const float4*)&qrow[a];
            s = fmaf(q4.x, krow[a], s);
            s = fmaf(q4.y, krow[a+1], s);
            s = fmaf(q4.z, krow[a+2], s);
            s = fmaf(q4.w, krow[a+3], s);
        }
        __half hi, lo; split_h(s, hi, lo);
        h[(size_t)f * 512 + e] = hi;
        l[(size_t)f * 512 + e] = lo;
    }
}

// N^T[e,f] = sum_a Wv[f,a] * Wo[a,e] -> fp16 split, layout [e*256+f]
__global__ __launch_bounds__(512)
void prep_NT(const float* __restrict__ Wv, const float* __restrict__ Wo,
             __half* __restrict__ h, __half* __restrict__ l)
{
    __shared__ float vrow[512];
    const int f = blockIdx.x;
    if (threadIdx.x < 512) vrow[threadIdx.x] = Wv[(size_t)f * 512 + threadIdx.x];
    __syncthreads();
    const int e = threadIdx.x;
    float s = 0.0f;
#pragma unroll 8
    for (int a = 0; a < 512; a++) s = fmaf(vrow[a], __ldg(&Wo[(size_t)a * 512 + e]), s);
    __half hi, lo; split_h(s, hi, lo);
    h[(size_t)e * 256 + f] = hi;
    l[(size_t)e * 256 + f] = lo;
}

// hv[f] = Wk[f,:] . bq
__global__ __launch_bounds__(256)
void prep_hv(const float* __restrict__ Wk, const float* __restrict__ bq,
             float* __restrict__ hv)
{
    const int f = threadIdx.x;
    float s = 0.0f;
    for (int a = 0; a < 512; a++) s = fmaf(Wk[(size_t)f * 512 + a], bq[a], s);
    hv[f] = s;
}

// wv[r] = Y[r,:] . hv
__global__ __launch_bounds__(256)
void prep_wv(const float* __restrict__ Y, const float* __restrict__ hv,
             float* __restrict__ wv)
{
    __shared__ float hs[256];
    if (threadIdx.x < 256) hs[threadIdx.x] = hv[threadIdx.x];
    __syncthreads();
    const int lane = threadIdx.x & 31;
    const int w = threadIdx.x >> 5;
    const size_t r = (size_t)blockIdx.x * 8 + w;
    const float* row = Y + r * 256;
    float s = 0.0f;
#pragma unroll
    for (int j = 0; j < 8; j++) s = fmaf(row[lane * 8 + j], hs[lane * 8 + j], s);
#pragma unroll
    for (int o = 16; o; o >>= 1) s += __shfl_xor_sync(0xffffffffu, s, o);
    if (lane == 0) wv[r] = s;
}

// ob[e] = bo[e] + bv . Wo[:,e]
__global__ __launch_bounds__(512)
void prep_ob(const float* __restrict__ bv, const float* __restrict__ Wo,
             const float* __restrict__ bo, float* __restrict__ ob)
{
    const int e = threadIdx.x;
    float s = bo[e];
    for (int a = 0; a < 512; a++) s = fmaf(bv[a], Wo[(size_t)a * 512 + e], s);
    ob[e] = s;
}

// ---------------------------------------------------------------------------
// Softmax over 2048-col fp32 rows -> hi/lo fp16 row-major
// ---------------------------------------------------------------------------
__global__ __launch_bounds__(256)
void softmax_split(const float* __restrict__ S, __half* __restrict__ Sh,
                   __half* __restrict__ Sl)
{
    const size_t r = blockIdx.x;
    const float* row = S + r * 2048;
    const int tid = threadIdx.x;
    const int c0 = tid * 8;

    float v[8];
    *(float4*)&v[0] = *(const float4*)&row[c0];
    *(float4*)&v[4] = *(const float4*)&row[c0 + 4];

    __shared__ float red[8];
    float m = v[0];
#pragma unroll
    for (int e = 1; e < 8; e++) m = fmaxf(m, v[e]);
#pragma unroll
    for (int o = 16; o; o >>= 1) m = fmaxf(m, __shfl_xor_sync(0xffffffffu, m, o));
    if ((tid & 31) == 0) red[tid >> 5] = m;
    __syncthreads();
    float mx = red[0];
#pragma unroll
    for (int i = 1; i < 8; i++) mx = fmaxf(mx, red[i]);
    __syncthreads();

    float s = 0.0f;
#pragma unroll
    for (int e = 0; e < 8; e++) { v[e] = __expf(v[e] - mx); s += v[e]; }
#pragma unroll
    for (int o = 16; o; o >>= 1) s += __shfl_xor_sync(0xffffffffu, s, o);
    if ((tid & 31) == 0) red[tid >> 5] = s;
    __syncthreads();
    float st = 0.0f;
#pragma unroll
    for (int i = 0; i < 8; i++) st += red[i];
    const float inv = 1.0f / st;

    __half hi[8], lo[8];
#pragma unroll
    for (int e = 0; e < 8; e++) split_h(v[e] * inv, hi[e], lo[e]);
    uint4 hv, lv;
    hv.x = pk2h(hi[0],hi[1]); hv.y = pk2h(hi[2],hi[3]); hv.z = pk2h(hi[4],hi[5]); hv.w = pk2h(hi[6],hi[7]);
    lv.x = pk2h(lo[0],lo[1]); lv.y = pk2h(lo[2],lo[3]); lv.z = pk2h(lo[4],lo[5]); lv.w = pk2h(lo[6],lo[7]);
    *(uint4*)&Sh[r * 2048 + c0] = hv;
    *(uint4*)&Sl[r * 2048 + c0] = lv;
}

// ---------------------------------------------------------------------------
// Launch
// ---------------------------------------------------------------------------
extern "C" void kernel_launch(void* const* d_in, const int* in_sizes, int n_in,
                              void* d_out, int out_size)
{
    const float* X  = (const float*)d_in[0];
    const float* Y  = (const float*)d_in[1];
    const float* Wq = (const float*)d_in[2];
    const float* bq = (const float*)d_in[3];
    const float* Wk = (const float*)d_in[4];
    const float* Wv = (const float*)d_in[6];
    const float* bv = (const float*)d_in[7];
    const float* Wo = (const float*)d_in[8];
    const float* bo = (const float*)d_in[9];
    float* out = (float*)d_out;

    constexpr int SMEM3 = STAGES * (2 * A_TILE_B + 2 * B_TILE_B);   // 184320
    constexpr int SMEM2 = STAGES * (2 * A_TILE_B + 1 * B_TILE_B);   // 122880
    cudaFuncSetAttribute(gemm_mma<3,0,1>, cudaFuncAttributeMaxDynamicSharedMemorySize, SMEM3);
    cudaFuncSetAttribute(gemm_mma<3,1,0>, cudaFuncAttributeMaxDynamicSharedMemorySize, SMEM3);
    cudaFuncSetAttribute(gemm_mma<3,0,2>, cudaFuncAttributeMaxDynamicSharedMemorySize, SMEM3);
    cudaFuncSetAttribute(gemm_mma<2,1,0>, cudaFuncAttributeMaxDynamicSharedMemorySize, SMEM2);

    __half *Xh,*Xl,*Yh,*Yl,*YTh,*YTl,*Mh,*Ml,*Nh,*Nl,*Th,*Tl,*Ph,*Pl,*Ch,*Cl;
    float *S,*hv,*wv,*ob;
    cudaGetSymbolAddress((void**)&Xh, g_Xh);   cudaGetSymbolAddress((void**)&Xl, g_Xl);
    cudaGetSymbolAddress((void**)&Yh, g_Yh);   cudaGetSymbolAddress((void**)&Yl, g_Yl);
    cudaGetSymbolAddress((void**)&YTh, g_YTh); cudaGetSymbolAddress((void**)&YTl, g_YTl);
    cudaGetSymbolAddress((void**)&Mh, g_Mh);   cudaGetSymbolAddress((void**)&Ml, g_Ml);
    cudaGetSymbolAddress((void**)&Nh, g_Nh);   cudaGetSymbolAddress((void**)&Nl, g_Nl);
    cudaGetSymbolAddress((void**)&Th, g_Th);   cudaGetSymbolAddress((void**)&Tl, g_Tl);
    cudaGetSymbolAddress((void**)&Ph, g_Ph);   cudaGetSymbolAddress((void**)&Pl, g_Pl);
    cudaGetSymbolAddress((void**)&Ch, g_Ch);   cudaGetSymbolAddress((void**)&Cl, g_Cl);
    cudaGetSymbolAddress((void**)&S, g_S);
    cudaGetSymbolAddress((void**)&hv, g_hv);
    cudaGetSymbolAddress((void**)&wv, g_wv);
    cudaGetSymbolAddress((void**)&ob, g_ob);

    // 1,2: input splits
    split_rm<<<4096, 256>>>(X, Xh, Xl, (size_t)16384*512/8);
    split_rm<<<4096, 256>>>(Y, Yh, Yl, (size_t)32768*256/8);
    // 3: Y^T split (for C = P@Y)
    transpose_split<<<dim3(32,4,16), 256>>>(Y, YTh, YTl);
    // 4: M^T
    prep_MT<<<256, 256>>>(Wq, Wk, Mh, Ml);
    // 5: T = X @ M -> split [16384,256]
    {
        GemmArgs a{Xh, Xl, Mh, Ml, nullptr, nullptr, Th, Tl,
                   512, 0, 0, 0, 256, 0};
        gemm_mma<3,1,0><<<dim3(1,128,1), 512, SMEM3>>>(a);
    }
    // 6,7: logit key-bias
    prep_hv<<<1, 256>>>(Wk, bq, hv);
    prep_wv<<<4096, 256>>>(Y, hv, wv);
    // 8: S = T_z @ Y_z^T + wv -> fp32 [1024,2048] x16
    {
        GemmArgs a{Th, Tl, Yh, Yl, wv, S, nullptr, nullptr,
                   256, (long long)1024*256, (long long)2048*256,
                   (long long)1024*2048, 2048, 2048};
        gemm_mma<3,0,1><<<dim3(8,8,16), 512, SMEM3>>>(a);
    }
    // 9: softmax -> P split
    softmax_split<<<16384, 256>>>(S, Ph, Pl);
    // 10: N^T
    prep_NT<<<256, 512>>>(Wv, Wo, Nh, Nl);
    // 11: C = (Ph+Pl) @ Yh -> split [1024,256] x16  (2-term)
    {
        GemmArgs a{Ph, Pl, YTh, nullptr, nullptr, nullptr, Ch, Cl,
                   2048, (long long)1024*2048, (long long)256*2048,
                   (long long)1024*256, 256, 0};
        gemm_mma<2,1,0><<<dim3(1,8,16), 512, SMEM2>>>(a);
    }
    // 12: output bias
    prep_ob<<<1, 512>>>(bv, Wo, bo, ob);
    // 13: out = C @ N + ob -> fp32 [16384,512]  (3-term)
    {
        GemmArgs a{Ch, Cl, Nh, Nl, ob, out, nullptr, nullptr,
                   256, 0, 0, 0, 512, 0};
        gemm_mma<3,0,1><<<dim3(2,128,1), 512, SMEM3>>>(a);
    }
}

// round 10
// speedup vs baseline: 1.3407x; 1.0994x over previous
#include <cuda_runtime.h>
#include <cuda_fp16.h>
#include <cstdint>
#include <cstddef>

// ---------------------------------------------------------------------------
// CrossAttention on sm_100 via mma.sync fp16 (HMMA), split fp32 accum.
// R10: tiled fp32 prep GEMMs (prep_MT 79us -> ~6us, prep_NT 25us -> ~8us).
//   S = X(WqWk^T)Y^T + wv ;  out = (P@Y)@(WvWo) + (bv·Wo+bo)
// ---------------------------------------------------------------------------

#define STAGES 3
#define BK 32
#define TROW 80                     // padded smem row bytes (40 fp16)
#define A_TILE_B (128 * TROW)       // 10240
#define B_TILE_B (256 * TROW)       // 20480

// ---------------- scratch (device globals) ---------------------------------
__device__ __half g_Xh[(size_t)16384*512],  g_Xl[(size_t)16384*512];
__device__ __half g_Yh[(size_t)32768*256],  g_Yl[(size_t)32768*256];
__device__ __half g_YTh[(size_t)16*256*2048], g_YTl[(size_t)16*256*2048];
__device__ __half g_Mh[256*512],  g_Ml[256*512];    // (WqWk^T)^T : [256f, 512e]
__device__ __half g_Nh[512*256],  g_Nl[512*256];    // (WvWo)^T   : [512e, 256f]
__device__ __half g_Th[(size_t)16384*256],  g_Tl[(size_t)16384*256];
__device__ float  g_S[(size_t)16*1024*2048];
__device__ __half g_Ph[(size_t)16384*2048], g_Pl[(size_t)16384*2048];
__device__ __half g_Ch[(size_t)16384*256],  g_Cl[(size_t)16384*256];
__device__ float  g_hv[256];       // Wk @ bq
__device__ float  g_wv[32768];     // Y @ (Wk @ bq)  (per-key logit bias)
__device__ float  g_ob[512];       // bv @ Wo + bo

// ---------------- helpers ---------------------------------------------------
__device__ __forceinline__ uint32_t smem_u32(const void* p) {
    uint32_t a;
    asm("{ .reg .u64 t; cvta.to.shared.u64 t, %1; cvt.u32.u64 %0, t; }"
        : "=r"(a) : "l"(p));
    return a;
}
__device__ __forceinline__ void cp16(uint32_t dst, const void* src) {
    asm volatile("cp.async.cg.shared.global [%0], [%1], 16;"
                 :: "r"(dst), "l"(src) : "memory");
}
__device__ __forceinline__ void cp_commit() {
    asm volatile("cp.async.commit_group;" ::: "memory");
}
__device__ __forceinline__ void cp_wait1() {
    asm volatile("cp.async.wait_group 1;" ::: "memory");
}
__device__ __forceinline__ void ldm4(uint32_t* r, uint32_t addr) {
    asm volatile("ldmatrix.sync.aligned.m8n8.x4.shared.b16 {%0,%1,%2,%3}, [%4];"
                 : "=r"(r[0]), "=r"(r[1]), "=r"(r[2]), "=r"(r[3]) : "r"(addr));
}
__device__ __forceinline__ void mma16816(float* d, const uint32_t* a,
                                         uint32_t b0, uint32_t b1) {
    asm volatile(
        "mma.sync.aligned.m16n8k16.row.col.f32.f16.f16.f32 "
        "{%0,%1,%2,%3}, {%4,%5,%6,%7}, {%8,%9}, {%0,%1,%2,%3};"
        : "+f"(d[0]), "+f"(d[1]), "+f"(d[2]), "+f"(d[3])
        : "r"(a[0]), "r"(a[1]), "r"(a[2]), "r"(a[3]), "r"(b0), "r"(b1));
}
__device__ __forceinline__ uint32_t pk2h(__half a, __half b) {
    return ((uint32_t)__half_as_ushort(b) << 16) | (uint32_t)__half_as_ushort(a);
}
__device__ __forceinline__ void split_h(float x, __half& hi, __half& lo) {
    hi = __float2half(x);
    lo = __float2half(x - __half2float(hi));
}

// ---------------------------------------------------------------------------
// Split-fp16 GEMM. A:[Mtot,K], B:[Ntot,K] row-major hi/lo.
// TERMS=3: D = AhBh + AlBh + AhBl.  TERMS=2: D = AhBh + AlBh (B hi only).
// Tile 128x256, BK=32, 3-stage cp.async, 16 warps (4Mx4N).
// EPI: 0 = fp32 out, 1 = split-fp16 out. BIAS: 0 none, 1 per-n (z-strided).
// ---------------------------------------------------------------------------
struct GemmArgs {
    const __half *Ah, *Al, *Bh, *Bl;
    const float* bias;
    float* outF;
    __half *outH, *outL;
    int K;
    long long aZ, bZ, outZ;
    int ldc;
    int biasZ;
};

template <int TERMS, int EPI, int BIAS>
__global__ __launch_bounds__(512, 1)
void gemm_mma(GemmArgs g)
{
    constexpr int OFF_AH = 0;
    constexpr int OFF_AL = A_TILE_B;
    constexpr int OFF_BH = 2 * A_TILE_B;
    constexpr int OFF_BL = 2 * A_TILE_B + B_TILE_B;        // TERMS==3 only
    constexpr int STAGE_B = 2 * A_TILE_B + (TERMS == 3 ? 2 : 1) * B_TILE_B;

    extern __shared__ char smem[];
    const uint32_t sm0 = smem_u32(smem);
    const int tid = threadIdx.x, lane = tid & 31, wid = tid >> 5;
    const int wm = wid & 3, wn = wid >> 2;
    const int z = blockIdx.z;
    const int m0 = blockIdx.y * 128, n0 = blockIdx.x * 256;
    const int K = g.K, nkt = K / BK;

    const __half* sAh = g.Ah + (size_t)z * g.aZ + (size_t)m0 * K;
    const __half* sAl = g.Al + (size_t)z * g.aZ + (size_t)m0 * K;
    const __half* sBh = g.Bh + (size_t)z * g.bZ + (size_t)n0 * K;
    const __half* sBl = (TERMS == 3) ? g.Bl + (size_t)z * g.bZ + (size_t)n0 * K : nullptr;
    const float* bp = (BIAS == 1) ? (g.bias + (size_t)z * g.biasZ) : nullptr;

    const int lr = tid >> 2, lc = tid & 3;

    float acc[2][8][4];
#pragma unroll
    for (int i = 0; i < 2; i++)
#pragma unroll
        for (int j = 0; j < 8; j++)
#pragma unroll
            for (int e = 0; e < 4; e++) acc[i][j][e] = 0.0f;

    const uint32_t aoff = (uint32_t)(wm * 32 + (lane & 7) + ((lane >> 3) & 1) * 8) * TROW
                        + (lane >> 4) * 16;
    const uint32_t boff = (uint32_t)(wn * 64 + (lane & 7) + ((lane >> 4) & 1) * 8) * TROW
                        + ((lane >> 3) & 1) * 16;

    auto load_stage = [&](int kt, int s) {
        const uint32_t stb = sm0 + s * STAGE_B;
        const size_t kofs = (size_t)kt * BK;
        const uint32_t drow = (uint32_t)lr * TROW + lc * 16;
        const size_t srow = (size_t)lr * K + kofs + lc * 8;
        cp16(stb + OFF_AH + drow, sAh + srow);
        cp16(stb + OFF_AL + drow, sAl + srow);
#pragma unroll
        for (int h = 0; h < 2; h++) {
            const uint32_t r = lr + h * 128;
            const uint32_t d2 = (uint32_t)r * TROW + lc * 16;
            const size_t s2 = (size_t)r * K + kofs + lc * 8;
            cp16(stb + OFF_BH + d2, sBh + s2);
            if (TERMS == 3) cp16(stb + OFF_BL + d2, sBl + s2);
        }
    };

    auto compute_stage = [&](int s) {
        const uint32_t stb = sm0 + s * STAGE_B;
#pragma unroll
        for (int ks = 0; ks < 2; ks++) {
            uint32_t aH[2][4], aL[2][4], bB[4][4];
#pragma unroll
            for (int mt = 0; mt < 2; mt++) {
                const uint32_t o = aoff + (uint32_t)mt * 16 * TROW + ks * 32;
                ldm4(aH[mt], stb + OFF_AH + o);
                ldm4(aL[mt], stb + OFF_AL + o);
            }
#pragma unroll
            for (int np = 0; np < 4; np++)
                ldm4(bB[np], stb + OFF_BH + boff + (uint32_t)np * 16 * TROW + ks * 32);
            // Ah @ Bh
#pragma unroll
            for (int mt = 0; mt < 2; mt++)
#pragma unroll
                for (int nt = 0; nt < 8; nt++) {
                    const uint32_t* b = &bB[nt >> 1][(nt & 1) * 2];
                    mma16816(acc[mt][nt], aH[mt], b[0], b[1]);
                }
            // Al @ Bh
#pragma unroll
            for (int mt = 0; mt < 2; mt++)
#pragma unroll
                for (int nt = 0; nt < 8; nt++) {
                    const uint32_t* b = &bB[nt >> 1][(nt & 1) * 2];
                    mma16816(acc[mt][nt], aL[mt], b[0], b[1]);
                }
            if (TERMS == 3) {
#pragma unroll
                for (int np = 0; np < 4; np++)
                    ldm4(bB[np], stb + OFF_BL + boff + (uint32_t)np * 16 * TROW + ks * 32);
#pragma unroll
                for (int mt = 0; mt < 2; mt++)
#pragma unroll
                    for (int nt = 0; nt < 8; nt++) {
                        const uint32_t* b = &bB[nt >> 1][(nt & 1) * 2];
                        mma16816(acc[mt][nt], aH[mt], b[0], b[1]);
                    }
            }
        }
    };

#pragma unroll
    for (int s = 0; s < STAGES - 1; s++) { load_stage(s, s); cp_commit(); }
    for (int kt = 0; kt < nkt; kt++) {
        cp_wait1();
        __syncthreads();
        const int nx = kt + STAGES - 1;
        if (nx < nkt) load_stage(nx, nx % STAGES);
        cp_commit();
        compute_stage(kt % STAGES);
    }

    // ---------------- epilogue --------------------------------------------
    const int rr = lane >> 2, rc = (lane & 3) * 2;
#pragma unroll
    for (int mt = 0; mt < 2; mt++) {
#pragma unroll
        for (int nt = 0; nt < 8; nt++) {
            float* d = acc[mt][nt];
            const int m = m0 + wm * 32 + mt * 16 + rr;
            const int n = n0 + wn * 64 + nt * 8 + rc;
            float v[4] = {d[0], d[1], d[2], d[3]};
            if (BIAS == 1) {
                const float b0v = bp[n], b1v = bp[n + 1];
                v[0] += b0v; v[1] += b1v; v[2] += b0v; v[3] += b1v;
            }
            if (EPI == 0) {
                float* o = g.outF + (size_t)z * g.outZ;
                *(float2*)&o[(size_t)m * g.ldc + n]       = make_float2(v[0], v[1]);
                *(float2*)&o[(size_t)(m + 8) * g.ldc + n] = make_float2(v[2], v[3]);
            } else {
                __half hi[4], lo[4];
#pragma unroll
                for (int e = 0; e < 4; e++) split_h(v[e], hi[e], lo[e]);
                __half* oh = g.outH + (size_t)z * g.outZ;
                __half* ol = g.outL + (size_t)z * g.outZ;
                *(uint32_t*)&oh[(size_t)m * g.ldc + n]       = pk2h(hi[0], hi[1]);
                *(uint32_t*)&oh[(size_t)(m + 8) * g.ldc + n] = pk2h(hi[2], hi[3]);
                *(uint32_t*)&ol[(size_t)m * g.ldc + n]       = pk2h(lo[0], lo[1]);
                *(uint32_t*)&ol[(size_t)(m + 8) * g.ldc + n] = pk2h(lo[2], lo[3]);
            }
        }
    }
}

// ---------------------------------------------------------------------------
// fp32 row-major -> hi/lo fp16 row-major
// ---------------------------------------------------------------------------
__global__ __launch_bounds__(256)
void split_rm(const float* __restrict__ in, __half* __restrict__ h,
              __half* __restrict__ l, size_t n8)
{
    const size_t id = (size_t)blockIdx.x * blockDim.x + threadIdx.x;
    if (id >= n8) return;
    float v[8];
    *(float4*)&v[0] = ((const float4*)in)[id * 2];
    *(float4*)&v[4] = ((const float4*)in)[id * 2 + 1];
    __half hi[8], lo[8];
#pragma unroll
    for (int e = 0; e < 8; e++) split_h(v[e], hi[e], lo[e]);
    uint4 hv, lv;
    hv.x = pk2h(hi[0],hi[1]); hv.y = pk2h(hi[2],hi[3]); hv.z = pk2h(hi[4],hi[5]); hv.w = pk2h(hi[6],hi[7]);
    lv.x = pk2h(lo[0],lo[1]); lv.y = pk2h(lo[2],lo[3]); lv.z = pk2h(lo[4],lo[5]); lv.w = pk2h(lo[6],lo[7]);
    *(uint4*)&h[id * 8] = hv;
    *(uint4*)&l[id * 8] = lv;
}

// ---------------------------------------------------------------------------
// Y [2048,256] fp32 per batch -> Y^T split fp16 [256,2048] per batch.
// ---------------------------------------------------------------------------
__global__ __launch_bounds__(256)
void transpose_split(const float* __restrict__ Y, __half* __restrict__ th,
                     __half* __restrict__ tl)
{
    __shared__ float t[64][65];
    const int z = blockIdx.z;
    const int k0 = blockIdx.x * 64;     // key offset
    const int f0 = blockIdx.y * 64;     // feature offset
    const float* Yb = Y + (size_t)z * 2048 * 256;
    const int tid = threadIdx.x;

    for (int i = tid; i < 64 * 16; i += 256) {
        const int r = i >> 4, c4 = i & 15;
        const float4 v = *(const float4*)&Yb[(size_t)(k0 + r) * 256 + f0 + c4 * 4];
        t[r][c4 * 4 + 0] = v.x; t[r][c4 * 4 + 1] = v.y;
        t[r][c4 * 4 + 2] = v.z; t[r][c4 * 4 + 3] = v.w;
    }
    __syncthreads();

    __half* thb = th + (size_t)z * 256 * 2048;
    __half* tlb = tl + (size_t)z * 256 * 2048;
    for (int i = tid; i < 64 * 16; i += 256) {
        const int f = i >> 4, c4 = i & 15;
        __half hi[4], lo[4];
#pragma unroll
        for (int e = 0; e < 4; e++) split_h(t[c4 * 4 + e][f], hi[e], lo[e]);
        uint2 hv, lv;
        hv.x = pk2h(hi[0], hi[1]); hv.y = pk2h(hi[2], hi[3]);
        lv.x = pk2h(lo[0], lo[1]); lv.y = pk2h(lo[2], lo[3]);
        *(uint2*)&thb[(size_t)(f0 + f) * 2048 + k0 + c4 * 4] = hv;
        *(uint2*)&tlb[(size_t)(f0 + f) * 2048 + k0 + c4 * 4] = lv;
    }
}

// ---------------------------------------------------------------------------
// prep_MT (tiled): MT[f,e] = sum_a Wk[f,a] * Wq[e,a] -> split fp16 [f*512+e]
// Block tile 32f x 64e, BK=64, 256 threads, 2x4 micro. Grid (8e, 8f).
// ---------------------------------------------------------------------------
__global__ __launch_bounds__(256)
void prep_MT(const float* __restrict__ Wq, const float* __restrict__ Wk,
             __half* __restrict__ h, __half* __restrict__ l)
{
    __shared__ float As[32][65];    // Wk[f][a]
    __shared__ float Bs[64][65];    // Wq[e][a]
    const int f0 = blockIdx.y * 32, e0 = blockIdx.x * 64;
    const int tid = threadIdx.x;
    const int tx = tid & 15, ty = tid >> 4;     // tx: e (x4), ty: f (x2)

    float acc[2][4] = {};
    for (int a0 = 0; a0 < 512; a0 += 64) {
#pragma unroll
        for (int it = 0; it < 2; it++) {
            const int idx = tid + it * 256;     // 0..511
            const int r = idx >> 4, c4 = idx & 15;
            const float4 v = *(const float4*)&Wk[(size_t)(f0 + r) * 512 + a0 + c4 * 4];
            As[r][c4*4+0] = v.x; As[r][c4*4+1] = v.y;
            As[r][c4*4+2] = v.z; As[r][c4*4+3] = v.w;
        }
#pragma unroll
        for (int it = 0; it < 4; it++) {
            const int idx = tid + it * 256;     // 0..1023
            const int r = idx >> 4, c4 = idx & 15;
            const float4 v = *(const float4*)&Wq[(size_t)(e0 + r) * 512 + a0 + c4 * 4];
            Bs[r][c4*4+0] = v.x; Bs[r][c4*4+1] = v.y;
            Bs[r][c4*4+2] = v.z; Bs[r][c4*4+3] = v.w;
        }
        __syncthreads();
#pragma unroll 8
        for (int a = 0; a < 64; a++) {
            const float a0v = As[ty*2][a], a1v = As[ty*2+1][a];
            float b[4];
#pragma unroll
            for (int j = 0; j < 4; j++) b[j] = Bs[tx*4+j][a];
#pragma unroll
            for (int j = 0; j < 4; j++) {
                acc[0][j] = fmaf(a0v, b[j], acc[0][j]);
                acc[1][j] = fmaf(a1v, b[j], acc[1][j]);
            }
        }
        __syncthreads();
    }
#pragma unroll
    for (int i = 0; i < 2; i++) {
        const int f = f0 + ty*2 + i;
        __half hi[4], lo[4];
#pragma unroll
        for (int j = 0; j < 4; j++) split_h(acc[i][j], hi[j], lo[j]);
        uint2 hv, lv;
        hv.x = pk2h(hi[0], hi[1]); hv.y = pk2h(hi[2], hi[3]);
        lv.x = pk2h(lo[0], lo[1]); lv.y = pk2h(lo[2], lo[3]);
        *(uint2*)&h[(size_t)f * 512 + e0 + tx*4] = hv;
        *(uint2*)&l[(size_t)f * 512 + e0 + tx*4] = lv;
    }
}

// ---------------------------------------------------------------------------
// prep_NT (tiled): NT[e,f] = sum_a Wo[a,e] * Wv[f,a] -> split fp16 [e*256+f]
// Block tile 64e x 32f, BK=64, 256 threads, 4x2 micro. Grid (8f, 8e).
// ---------------------------------------------------------------------------
__global__ __launch_bounds__(256)
void prep_NT(const float* __restrict__ Wv, const float* __restrict__ Wo,
             __half* __restrict__ h, __half* __restrict__ l)
{
    __shared__ float Os[64][65];    // Wo[a][e]   (a-local, e-local)
    __shared__ float Vs[32][65];    // Wv[f][a]
    const int f0 = blockIdx.x * 32, e0 = blockIdx.y * 64;
    const int tid = threadIdx.x;
    const int tx = tid & 15, ty = tid >> 4;     // tx: f (x2), ty: e (x4)

    float acc[4][2] = {};
    for (int a0 = 0; a0 < 512; a0 += 64) {
#pragma unroll
        for (int it = 0; it < 4; it++) {
            const int idx = tid + it * 256;     // 0..1023 : 64a x 16 float4 of e
            const int r = idx >> 4, c4 = idx & 15;
            const float4 v = *(const float4*)&Wo[(size_t)(a0 + r) * 512 + e0 + c4 * 4];
            Os[r][c4*4+0] = v.x; Os[r][c4*4+1] = v.y;
            Os[r][c4*4+2] = v.z; Os[r][c4*4+3] = v.w;
        }
#pragma unroll
        for (int it = 0; it < 2; it++) {
            const int idx = tid + it * 256;     // 0..511 : 32f x 16 float4 of a
            const int r = idx >> 4, c4 = idx & 15;
            const float4 v = *(const float4*)&Wv[(size_t)(f0 + r) * 512 + a0 + c4 * 4];
            Vs[r][c4*4+0] = v.x; Vs[r][c4*4+1] = v.y;
            Vs[r][c4*4+2] = v.z; Vs[r][c4*4+3] = v.w;
        }
        __syncthreads();
#pragma unroll 8
        for (int a = 0; a < 64; a++) {
            float e4[4], fv0, fv1;
#pragma unroll
            for (int i = 0; i < 4; i++) e4[i] = Os[a][ty*4+i];    // Wo[a][e] transposed read
            fv0 = Vs[tx*2][a]; fv1 = Vs[tx*2+1][a];
#pragma unroll
            for (int i = 0; i < 4; i++) {
                acc[i][0] = fmaf(e4[i], fv0, acc[i][0]);
                acc[i][1] = fmaf(e4[i], fv1, acc[i][1]);
            }
        }
        __syncthreads();
    }
#pragma unroll
    for (int i = 0; i < 4; i++) {
        const int e = e0 + ty*4 + i;
        __half hi[2], lo[2];
#pragma unroll
        for (int j = 0; j < 2; j++) split_h(acc[i][j], hi[j], lo[j]);
        *(uint32_t*)&h[(size_t)e * 256 + f0 + tx*2] = pk2h(hi[0], hi[1]);
        *(uint32_t*)&l[(size_t)e * 256 + f0 + tx*2] = pk2h(lo[0], lo[1]);
    }
}

// hv[f] = Wk[f,:] . bq
__global__ __launch_bounds__(256)
void prep_hv(const float* __restrict__ Wk, const float* __restrict__ bq,
             float* __restrict__ hv)
{
    const int f = threadIdx.x;
    float s = 0.0f;
    for (int a = 0; a < 512; a++) s = fmaf(Wk[(size_t)f * 512 + a], bq[a], s);
    hv[f] = s;
}

// wv[r] = Y[r,:] . hv
__global__ __launch_bounds__(256)
void prep_wv(const float* __restrict__ Y, const float* __restrict__ hv,
             float* __restrict__ wv)
{
    __shared__ float hs[256];
    if (threadIdx.x < 256) hs[threadIdx.x] = hv[threadIdx.x];
    __syncthreads();
    const int lane = threadIdx.x & 31;
    const int w = threadIdx.x >> 5;
    const size_t r = (size_t)blockIdx.x * 8 + w;
    const float* row = Y + r * 256;
    float s = 0.0f;
#pragma unroll
    for (int j = 0; j < 8; j++) s = fmaf(row[lane * 8 + j], hs[lane * 8 + j], s);
#pragma unroll
    for (int o = 16; o; o >>= 1) s += __shfl_xor_sync(0xffffffffu, s, o);
    if (lane == 0) wv[r] = s;
}

// ob[e] = bo[e] + bv . Wo[:,e]
__global__ __launch_bounds__(512)
void prep_ob(const float* __restrict__ bv, const float* __restrict__ Wo,
             const float* __restrict__ bo, float* __restrict__ ob)
{
    const int e = threadIdx.x;
    float s = bo[e];
    for (int a = 0; a < 512; a++) s = fmaf(bv[a], Wo[(size_t)a * 512 + e], s);
    ob[e] = s;
}

// ---------------------------------------------------------------------------
// Softmax over 2048-col fp32 rows -> hi/lo fp16 row-major
// ---------------------------------------------------------------------------
__global__ __launch_bounds__(256)
void softmax_split(const float* __restrict__ S, __half* __restrict__ Sh,
                   __half* __restrict__ Sl)
{
    const size_t r = blockIdx.x;
    const float* row = S + r * 2048;
    const int tid = threadIdx.x;
    const int c0 = tid * 8;

    float v[8];
    *(float4*)&v[0] = *(const float4*)&row[c0];
    *(float4*)&v[4] = *(const float4*)&row[c0 + 4];

    __shared__ float red[8];
    float m = v[0];
#pragma unroll
    for (int e = 1; e < 8; e++) m = fmaxf(m, v[e]);
#pragma unroll
    for (int o = 16; o; o >>= 1) m = fmaxf(m, __shfl_xor_sync(0xffffffffu, m, o));
    if ((tid & 31) == 0) red[tid >> 5] = m;
    __syncthreads();
    float mx = red[0];
#pragma unroll
    for (int i = 1; i < 8; i++) mx = fmaxf(mx, red[i]);
    __syncthreads();

    float s = 0.0f;
#pragma unroll
    for (int e = 0; e < 8; e++) { v[e] = __expf(v[e] - mx); s += v[e]; }
#pragma unroll
    for (int o = 16; o; o >>= 1) s += __shfl_xor_sync(0xffffffffu, s, o);
    if ((tid & 31) == 0) red[tid >> 5] = s;
    __syncthreads();
    float st = 0.0f;
#pragma unroll
    for (int i = 0; i < 8; i++) st += red[i];
    const float inv = 1.0f / st;

    __half hi[8], lo[8];
#pragma unroll
    for (int e = 0; e < 8; e++) split_h(v[e] * inv, hi[e], lo[e]);
    uint4 hv, lv;
    hv.x = pk2h(hi[0],hi[1]); hv.y = pk2h(hi[2],hi[3]); hv.z = pk2h(hi[4],hi[5]); hv.w = pk2h(hi[6],hi[7]);
    lv.x = pk2h(lo[0],lo[1]); lv.y = pk2h(lo[2],lo[3]); lv.z = pk2h(lo[4],lo[5]); lv.w = pk2h(lo[6],lo[7]);
    *(uint4*)&Sh[r * 2048 + c0] = hv;
    *(uint4*)&Sl[r * 2048 + c0] = lv;
}

// ---------------------------------------------------------------------------
// Launch
// ---------------------------------------------------------------------------
extern "C" void kernel_launch(void* const* d_in, const int* in_sizes, int n_in,
                              void* d_out, int out_size)
{
    const float* X  = (const float*)d_in[0];
    const float* Y  = (const float*)d_in[1];
    const float* Wq = (const float*)d_in[2];
    const float* bq = (const float*)d_in[3];
    const float* Wk = (const float*)d_in[4];
    const float* Wv = (const float*)d_in[6];
    const float* bv = (const float*)d_in[7];
    const float* Wo = (const float*)d_in[8];
    const float* bo = (const float*)d_in[9];
    float* out = (float*)d_out;

    constexpr int SMEM3 = STAGES * (2 * A_TILE_B + 2 * B_TILE_B);   // 184320
    constexpr int SMEM2 = STAGES * (2 * A_TILE_B + 1 * B_TILE_B);   // 122880
    cudaFuncSetAttribute(gemm_mma<3,0,1>, cudaFuncAttributeMaxDynamicSharedMemorySize, SMEM3);
    cudaFuncSetAttribute(gemm_mma<3,1,0>, cudaFuncAttributeMaxDynamicSharedMemorySize, SMEM3);
    cudaFuncSetAttribute(gemm_mma<2,1,0>, cudaFuncAttributeMaxDynamicSharedMemorySize, SMEM2);

    __half *Xh,*Xl,*Yh,*Yl,*YTh,*YTl,*Mh,*Ml,*Nh,*Nl,*Th,*Tl,*Ph,*Pl,*Ch,*Cl;
    float *S,*hv,*wv,*ob;
    cudaGetSymbolAddress((void**)&Xh, g_Xh);   cudaGetSymbolAddress((void**)&Xl, g_Xl);
    cudaGetSymbolAddress((void**)&Yh, g_Yh);   cudaGetSymbolAddress((void**)&Yl, g_Yl);
    cudaGetSymbolAddress((void**)&YTh, g_YTh); cudaGetSymbolAddress((void**)&YTl, g_YTl);
    cudaGetSymbolAddress((void**)&Mh, g_Mh);   cudaGetSymbolAddress((void**)&Ml, g_Ml);
    cudaGetSymbolAddress((void**)&Nh, g_Nh);   cudaGetSymbolAddress((void**)&Nl, g_Nl);
    cudaGetSymbolAddress((void**)&Th, g_Th);   cudaGetSymbolAddress((void**)&Tl, g_Tl);
    cudaGetSymbolAddress((void**)&Ph, g_Ph);   cudaGetSymbolAddress((void**)&Pl, g_Pl);
    cudaGetSymbolAddress((void**)&Ch, g_Ch);   cudaGetSymbolAddress((void**)&Cl, g_Cl);
    cudaGetSymbolAddress((void**)&S, g_S);
    cudaGetSymbolAddress((void**)&hv, g_hv);
    cudaGetSymbolAddress((void**)&wv, g_wv);
    cudaGetSymbolAddress((void**)&ob, g_ob);

    // 1,2: input splits
    split_rm<<<4096, 256>>>(X, Xh, Xl, (size_t)16384*512/8);
    split_rm<<<4096, 256>>>(Y, Yh, Yl, (size_t)32768*256/8);
    // 3: Y^T split (for C = P@Y)
    transpose_split<<<dim3(32,4,16), 256>>>(Y, YTh, YTl);
    // 4: M^T (tiled)
    prep_MT<<<dim3(8,8), 256>>>(Wq, Wk, Mh, Ml);
    // 5: T = X @ M -> split [16384,256]
    {
        GemmArgs a{Xh, Xl, Mh, Ml, nullptr, nullptr, Th, Tl,
                   512, 0, 0, 0, 256, 0};
        gemm_mma<3,1,0><<<dim3(1,128,1), 512, SMEM3>>>(a);
    }
    // 6,7: logit key-bias
    prep_hv<<<1, 256>>>(Wk, bq, hv);
    prep_wv<<<4096, 256>>>(Y, hv, wv);
    // 8: S = T_z @ Y_z^T + wv -> fp32 [1024,2048] x16
    {
        GemmArgs a{Th, Tl, Yh, Yl, wv, S, nullptr, nullptr,
                   256, (long long)1024*256, (long long)2048*256,
                   (long long)1024*2048, 2048, 2048};
        gemm_mma<3,0,1><<<dim3(8,8,16), 512, SMEM3>>>(a);
    }
    // 9: softmax -> P split
    softmax_split<<<16384, 256>>>(S, Ph, Pl);
    // 10: N^T (tiled)
    prep_NT<<<dim3(8,8), 256>>>(Wv, Wo, Nh, Nl);
    // 11: C = (Ph+Pl) @ Yh -> split [1024,256] x16  (2-term)
    {
        GemmArgs a{Ph, Pl, YTh, nullptr, nullptr, nullptr, Ch, Cl,
                   2048, (long long)1024*2048, (long long)256*2048,
                   (long long)1024*256, 256, 0};
        gemm_mma<2,1,0><<<dim3(1,8,16), 512, SMEM2>>>(a);
    }
    // 12: output bias
    prep_ob<<<1, 512>>>(bv, Wo, bo, ob);
    // 13: out = C @ N + ob -> fp32 [16384,512]  (3-term)
    {
        GemmArgs a{Ch, Cl, Nh, Nl, ob, out, nullptr, nullptr,
                   256, 0, 0, 0, 512, 0};
        gemm_mma<3,0,1><<<dim3(2,128,1), 512, SMEM3>>>(a);
    }
}

// round 12
// speedup vs baseline: 1.4718x; 1.0978x over previous
#include <cuda_runtime.h>
#include <cuda_fp16.h>
#include <cstdint>
#include <cstddef>

// ---------------------------------------------------------------------------
// CrossAttention on sm_100 via mma.sync fp16 (HMMA), split fp32 accum.
// R12: all independent prep kernels fused into ONE mega-kernel (blockIdx
// dispatch) — overlap without streams (R11's streams tripped the alloc guard).
//   S = X(WqWk^T)Y^T + wv ;  out = (P@Y)@(WvWo) + (bv·Wo+bo)
// ---------------------------------------------------------------------------

#define STAGES 3
#define BK 32
#define TROW 80                     // padded smem row bytes (40 fp16)
#define A_TILE_B (128 * TROW)       // 10240
#define B_TILE_B (256 * TROW)       // 20480

// ---------------- scratch (device globals) ---------------------------------
__device__ __half g_Xh[(size_t)16384*512],  g_Xl[(size_t)16384*512];
__device__ __half g_Yh[(size_t)32768*256],  g_Yl[(size_t)32768*256];
__device__ __half g_YTh[(size_t)16*256*2048], g_YTl[(size_t)16*256*2048];
__device__ __half g_Mh[256*512],  g_Ml[256*512];    // (WqWk^T)^T : [256f, 512e]
__device__ __half g_Nh[512*256],  g_Nl[512*256];    // (WvWo)^T   : [512e, 256f]
__device__ __half g_Th[(size_t)16384*256],  g_Tl[(size_t)16384*256];
__device__ float  g_S[(size_t)16*1024*2048];
__device__ __half g_Ph[(size_t)16384*2048], g_Pl[(size_t)16384*2048];
__device__ __half g_Ch[(size_t)16384*256],  g_Cl[(size_t)16384*256];
__device__ float  g_hv[256];       // Wk @ bq
__device__ float  g_wv[32768];     // Y @ (Wk @ bq)  (per-key logit bias)
__device__ float  g_ob[512];       // bv @ Wo + bo

// ---------------- helpers ---------------------------------------------------
__device__ __forceinline__ uint32_t smem_u32(const void* p) {
    uint32_t a;
    asm("{ .reg .u64 t; cvta.to.shared.u64 t, %1; cvt.u32.u64 %0, t; }"
        : "=r"(a) : "l"(p));
    return a;
}
__device__ __forceinline__ void cp16(uint32_t dst, const void* src) {
    asm volatile("cp.async.cg.shared.global [%0], [%1], 16;"
                 :: "r"(dst), "l"(src) : "memory");
}
__device__ __forceinline__ void cp_commit() {
    asm volatile("cp.async.commit_group;" ::: "memory");
}
__device__ __forceinline__ void cp_wait1() {
    asm volatile("cp.async.wait_group 1;" ::: "memory");
}
__device__ __forceinline__ void ldm4(uint32_t* r, uint32_t addr) {
    asm volatile("ldmatrix.sync.aligned.m8n8.x4.shared.b16 {%0,%1,%2,%3}, [%4];"
                 : "=r"(r[0]), "=r"(r[1]), "=r"(r[2]), "=r"(r[3]) : "r"(addr));
}
__device__ __forceinline__ void mma16816(float* d, const uint32_t* a,
                                         uint32_t b0, uint32_t b1) {
    asm volatile(
        "mma.sync.aligned.m16n8k16.row.col.f32.f16.f16.f32 "
        "{%0,%1,%2,%3}, {%4,%5,%6,%7}, {%8,%9}, {%0,%1,%2,%3};"
        : "+f"(d[0]), "+f"(d[1]), "+f"(d[2]), "+f"(d[3])
        : "r"(a[0]), "r"(a[1]), "r"(a[2]), "r"(a[3]), "r"(b0), "r"(b1));
}
__device__ __forceinline__ uint32_t pk2h(__half a, __half b) {
    return ((uint32_t)__half_as_ushort(b) << 16) | (uint32_t)__half_as_ushort(a);
}
__device__ __forceinline__ void split_h(float x, __half& hi, __half& lo) {
    hi = __float2half(x);
    lo = __float2half(x - __half2float(hi));
}

// ---------------------------------------------------------------------------
// Split-fp16 GEMM. A:[Mtot,K], B:[Ntot,K] row-major hi/lo.
// TERMS=3: D = AhBh + AlBh + AhBl.  TERMS=2: D = AhBh + AlBh (B hi only).
// Tile 128x256, BK=32, 3-stage cp.async, 16 warps (4Mx4N).
// EPI: 0 = fp32 out, 1 = split-fp16 out. BIAS: 0 none, 1 per-n (z-strided).
// ---------------------------------------------------------------------------
struct GemmArgs {
    const __half *Ah, *Al, *Bh, *Bl;
    const float* bias;
    float* outF;
    __half *outH, *outL;
    int K;
    long long aZ, bZ, outZ;
    int ldc;
    int biasZ;
};

template <int TERMS, int EPI, int BIAS>
__global__ __launch_bounds__(512, 1)
void gemm_mma(GemmArgs g)
{
    constexpr int OFF_AH = 0;
    constexpr int OFF_AL = A_TILE_B;
    constexpr int OFF_BH = 2 * A_TILE_B;
    constexpr int OFF_BL = 2 * A_TILE_B + B_TILE_B;        // TERMS==3 only
    constexpr int STAGE_B = 2 * A_TILE_B + (TERMS == 3 ? 2 : 1) * B_TILE_B;

    extern __shared__ char smem[];
    const uint32_t sm0 = smem_u32(smem);
    const int tid = threadIdx.x, lane = tid & 31, wid = tid >> 5;
    const int wm = wid & 3, wn = wid >> 2;
    const int z = blockIdx.z;
    const int m0 = blockIdx.y * 128, n0 = blockIdx.x * 256;
    const int K = g.K, nkt = K / BK;

    const __half* sAh = g.Ah + (size_t)z * g.aZ + (size_t)m0 * K;
    const __half* sAl = g.Al + (size_t)z * g.aZ + (size_t)m0 * K;
    const __half* sBh = g.Bh + (size_t)z * g.bZ + (size_t)n0 * K;
    const __half* sBl = (TERMS == 3) ? g.Bl + (size_t)z * g.bZ + (size_t)n0 * K : nullptr;
    const float* bp = (BIAS == 1) ? (g.bias + (size_t)z * g.biasZ) : nullptr;

    const int lr = tid >> 2, lc = tid & 3;

    float acc[2][8][4];
#pragma unroll
    for (int i = 0; i < 2; i++)
#pragma unroll
        for (int j = 0; j < 8; j++)
#pragma unroll
            for (int e = 0; e < 4; e++) acc[i][j][e] = 0.0f;

    const uint32_t aoff = (uint32_t)(wm * 32 + (lane & 7) + ((lane >> 3) & 1) * 8) * TROW
                        + (lane >> 4) * 16;
    const uint32_t boff = (uint32_t)(wn * 64 + (lane & 7) + ((lane >> 4) & 1) * 8) * TROW
                        + ((lane >> 3) & 1) * 16;

    auto load_stage = [&](int kt, int s) {
        const uint32_t stb = sm0 + s * STAGE_B;
        const size_t kofs = (size_t)kt * BK;
        const uint32_t drow = (uint32_t)lr * TROW + lc * 16;
        const size_t srow = (size_t)lr * K + kofs + lc * 8;
        cp16(stb + OFF_AH + drow, sAh + srow);
        cp16(stb + OFF_AL + drow, sAl + srow);
#pragma unroll
        for (int h = 0; h < 2; h++) {
            const uint32_t r = lr + h * 128;
            const uint32_t d2 = (uint32_t)r * TROW + lc * 16;
            const size_t s2 = (size_t)r * K + kofs + lc * 8;
            cp16(stb + OFF_BH + d2, sBh + s2);
            if (TERMS == 3) cp16(stb + OFF_BL + d2, sBl + s2);
        }
    };

    auto compute_stage = [&](int s) {
        const uint32_t stb = sm0 + s * STAGE_B;
#pragma unroll
        for (int ks = 0; ks < 2; ks++) {
            uint32_t aH[2][4], aL[2][4], bB[4][4];
#pragma unroll
            for (int mt = 0; mt < 2; mt++) {
                const uint32_t o = aoff + (uint32_t)mt * 16 * TROW + ks * 32;
                ldm4(aH[mt], stb + OFF_AH + o);
                ldm4(aL[mt], stb + OFF_AL + o);
            }
#pragma unroll
            for (int np = 0; np < 4; np++)
                ldm4(bB[np], stb + OFF_BH + boff + (uint32_t)np * 16 * TROW + ks * 32);
            // Ah @ Bh
#pragma unroll
            for (int mt = 0; mt < 2; mt++)
#pragma unroll
                for (int nt = 0; nt < 8; nt++) {
                    const uint32_t* b = &bB[nt >> 1][(nt & 1) * 2];
                    mma16816(acc[mt][nt], aH[mt], b[0], b[1]);
                }
            // Al @ Bh
#pragma unroll
            for (int mt = 0; mt < 2; mt++)
#pragma unroll
                for (int nt = 0; nt < 8; nt++) {
                    const uint32_t* b = &bB[nt >> 1][(nt & 1) * 2];
                    mma16816(acc[mt][nt], aL[mt], b[0], b[1]);
                }
            if (TERMS == 3) {
#pragma unroll
                for (int np = 0; np < 4; np++)
                    ldm4(bB[np], stb + OFF_BL + boff + (uint32_t)np * 16 * TROW + ks * 32);
#pragma unroll
                for (int mt = 0; mt < 2; mt++)
#pragma unroll
                    for (int nt = 0; nt < 8; nt++) {
                        const uint32_t* b = &bB[nt >> 1][(nt & 1) * 2];
                        mma16816(acc[mt][nt], aH[mt], b[0], b[1]);
                    }
            }
        }
    };

#pragma unroll
    for (int s = 0; s < STAGES - 1; s++) { load_stage(s, s); cp_commit(); }
    for (int kt = 0; kt < nkt; kt++) {
        cp_wait1();
        __syncthreads();
        const int nx = kt + STAGES - 1;
        if (nx < nkt) load_stage(nx, nx % STAGES);
        cp_commit();
        compute_stage(kt % STAGES);
    }

    // ---------------- epilogue --------------------------------------------
    const int rr = lane >> 2, rc = (lane & 3) * 2;
#pragma unroll
    for (int mt = 0; mt < 2; mt++) {
#pragma unroll
        for (int nt = 0; nt < 8; nt++) {
            float* d = acc[mt][nt];
            const int m = m0 + wm * 32 + mt * 16 + rr;
            const int n = n0 + wn * 64 + nt * 8 + rc;
            float v[4] = {d[0], d[1], d[2], d[3]};
            if (BIAS == 1) {
                const float b0v = bp[n], b1v = bp[n + 1];
                v[0] += b0v; v[1] += b1v; v[2] += b0v; v[3] += b1v;
            }
            if (EPI == 0) {
                float* o = g.outF + (size_t)z * g.outZ;
                *(float2*)&o[(size_t)m * g.ldc + n]       = make_float2(v[0], v[1]);
                *(float2*)&o[(size_t)(m + 8) * g.ldc + n] = make_float2(v[2], v[3]);
            } else {
                __half hi[4], lo[4];
#pragma unroll
                for (int e = 0; e < 4; e++) split_h(v[e], hi[e], lo[e]);
                __half* oh = g.outH + (size_t)z * g.outZ;
                __half* ol = g.outL + (size_t)z * g.outZ;
                *(uint32_t*)&oh[(size_t)m * g.ldc + n]       = pk2h(hi[0], hi[1]);
                *(uint32_t*)&oh[(size_t)(m + 8) * g.ldc + n] = pk2h(hi[2], hi[3]);
                *(uint32_t*)&ol[(size_t)m * g.ldc + n]       = pk2h(lo[0], lo[1]);
                *(uint32_t*)&ol[(size_t)(m + 8) * g.ldc + n] = pk2h(lo[2], lo[3]);
            }
        }
    }
}

// ---------------------------------------------------------------------------
// prep_hv: hv[f] = Wk[f,:] . bq  (single block; launched before fused prep)
// ---------------------------------------------------------------------------
__global__ __launch_bounds__(256)
void prep_hv(const float* __restrict__ Wk, const float* __restrict__ bq,
             float* __restrict__ hv)
{
    const int f = threadIdx.x;
    float s = 0.0f;
    for (int a = 0; a < 512; a++) s = fmaf(Wk[(size_t)f * 512 + a], bq[a], s);
    hv[f] = s;
}

// ---------------------------------------------------------------------------
// Fused prep mega-kernel: blockIdx.x ranges dispatch independent jobs.
//  [0,4096)        splitX
//  [4096,8192)     splitY
//  [8192,10240)    transpose_split (2048 blocks)
//  [10240,10304)   prep_MT (64)
//  [10304,14400)   prep_wv (4096)
//  [14400,14464)   prep_NT (64)
//  [14464]         prep_ob (1)
// ---------------------------------------------------------------------------
#define FP_SPLITX0   0
#define FP_SPLITY0   4096
#define FP_TRANS0    8192
#define FP_MT0       10240
#define FP_WV0       10304
#define FP_NT0       14400
#define FP_OB0       14464
#define FP_NBLK      14465

struct PrepArgs {
    const float *X, *Y, *Wq, *Wk, *Wv, *Wo, *bv, *bo, *hv;
    __half *Xh, *Xl, *Yh, *Yl, *YTh, *YTl, *Mh, *Ml, *Nh, *Nl;
    float *wv, *ob;
};

__global__ __launch_bounds__(256)
void fused_prep(PrepArgs p)
{
    __shared__ __align__(16) char smbuf[24960];
    const int blk = blockIdx.x;
    const int tid = threadIdx.x;

    if (blk < FP_SPLITY0) {
        // ---- splitX: [16384,512] fp32 -> hi/lo fp16, 8 floats per thread
        const size_t id = (size_t)(blk - FP_SPLITX0) * 256 + tid;
        float v[8];
        *(float4*)&v[0] = ((const float4*)p.X)[id * 2];
        *(float4*)&v[4] = ((const float4*)p.X)[id * 2 + 1];
        __half hi[8], lo[8];
#pragma unroll
        for (int e = 0; e < 8; e++) split_h(v[e], hi[e], lo[e]);
        uint4 hv4, lv4;
        hv4.x = pk2h(hi[0],hi[1]); hv4.y = pk2h(hi[2],hi[3]);
        hv4.z = pk2h(hi[4],hi[5]); hv4.w = pk2h(hi[6],hi[7]);
        lv4.x = pk2h(lo[0],lo[1]); lv4.y = pk2h(lo[2],lo[3]);
        lv4.z = pk2h(lo[4],lo[5]); lv4.w = pk2h(lo[6],lo[7]);
        *(uint4*)&p.Xh[id * 8] = hv4;
        *(uint4*)&p.Xl[id * 8] = lv4;
    } else if (blk < FP_TRANS0) {
        // ---- splitY: [32768,256]
        const size_t id = (size_t)(blk - FP_SPLITY0) * 256 + tid;
        float v[8];
        *(float4*)&v[0] = ((const float4*)p.Y)[id * 2];
        *(float4*)&v[4] = ((const float4*)p.Y)[id * 2 + 1];
        __half hi[8], lo[8];
#pragma unroll
        for (int e = 0; e < 8; e++) split_h(v[e], hi[e], lo[e]);
        uint4 hv4, lv4;
        hv4.x = pk2h(hi[0],hi[1]); hv4.y = pk2h(hi[2],hi[3]);
        hv4.z = pk2h(hi[4],hi[5]); hv4.w = pk2h(hi[6],hi[7]);
        lv4.x = pk2h(lo[0],lo[1]); lv4.y = pk2h(lo[2],lo[3]);
        lv4.z = pk2h(lo[4],lo[5]); lv4.w = pk2h(lo[6],lo[7]);
        *(uint4*)&p.Yh[id * 8] = hv4;
        *(uint4*)&p.Yl[id * 8] = lv4;
    } else if (blk < FP_MT0) {
        // ---- transpose_split: Y [2048,256] -> Y^T split [256,2048] x16
        float (*t)[65] = (float(*)[65])smbuf;            // 64x65 floats
        const int idx = blk - FP_TRANS0;
        const int z  = idx >> 7;             // 16
        const int r7 = idx & 127;
        const int k0 = (r7 >> 2) * 64;       // 32 tiles of keys
        const int f0 = (r7 & 3) * 64;        // 4 tiles of features
        const float* Yb = p.Y + (size_t)z * 2048 * 256;

        for (int i = tid; i < 64 * 16; i += 256) {
            const int r = i >> 4, c4 = i & 15;
            const float4 v = *(const float4*)&Yb[(size_t)(k0 + r) * 256 + f0 + c4 * 4];
            t[r][c4 * 4 + 0] = v.x; t[r][c4 * 4 + 1] = v.y;
            t[r][c4 * 4 + 2] = v.z; t[r][c4 * 4 + 3] = v.w;
        }
        __syncthreads();
        __half* thb = p.YTh + (size_t)z * 256 * 2048;
        __half* tlb = p.YTl + (size_t)z * 256 * 2048;
        for (int i = tid; i < 64 * 16; i += 256) {
            const int f = i >> 4, c4 = i & 15;
            __half hi[4], lo[4];
#pragma unroll
            for (int e = 0; e < 4; e++) split_h(t[c4 * 4 + e][f], hi[e], lo[e]);
            uint2 hv2, lv2;
            hv2.x = pk2h(hi[0], hi[1]); hv2.y = pk2h(hi[2], hi[3]);
            lv2.x = pk2h(lo[0], lo[1]); lv2.y = pk2h(lo[2], lo[3]);
            *(uint2*)&thb[(size_t)(f0 + f) * 2048 + k0 + c4 * 4] = hv2;
            *(uint2*)&tlb[(size_t)(f0 + f) * 2048 + k0 + c4 * 4] = lv2;
        }
    } else if (blk < FP_WV0) {
        // ---- prep_MT: MT[f,e] = Wk[f,:]·Wq[e,:]  (32f x 64e tile)
        float (*As)[65] = (float(*)[65])smbuf;                    // 32x65
        float (*Bs)[65] = (float(*)[65])(smbuf + 32*65*4);        // 64x65
        const int idx = blk - FP_MT0;
        const int e0 = (idx & 7) * 64, f0 = (idx >> 3) * 32;
        const int tx = tid & 15, ty = tid >> 4;

        float acc[2][4] = {};
        for (int a0 = 0; a0 < 512; a0 += 64) {
#pragma unroll
            for (int it = 0; it < 2; it++) {
                const int j = tid + it * 256;
                const int r = j >> 4, c4 = j & 15;
                const float4 v = *(const float4*)&p.Wk[(size_t)(f0 + r) * 512 + a0 + c4 * 4];
                As[r][c4*4+0] = v.x; As[r][c4*4+1] = v.y;
                As[r][c4*4+2] = v.z; As[r][c4*4+3] = v.w;
            }
#pragma unroll
            for (int it = 0; it < 4; it++) {
                const int j = tid + it * 256;
                const int r = j >> 4, c4 = j & 15;
                const float4 v = *(const float4*)&p.Wq[(size_t)(e0 + r) * 512 + a0 + c4 * 4];
                Bs[r][c4*4+0] = v.x; Bs[r][c4*4+1] = v.y;
                Bs[r][c4*4+2] = v.z; Bs[r][c4*4+3] = v.w;
            }
            __syncthreads();
#pragma unroll 8
            for (int a = 0; a < 64; a++) {
                const float a0v = As[ty*2][a], a1v = As[ty*2+1][a];
                float b[4];
#pragma unroll
                for (int j = 0; j < 4; j++) b[j] = Bs[tx*4+j][a];
#pragma unroll
                for (int j = 0; j < 4; j++) {
                    acc[0][j] = fmaf(a0v, b[j], acc[0][j]);
                    acc[1][j] = fmaf(a1v, b[j], acc[1][j]);
                }
            }
            __syncthreads();
        }
#pragma unroll
        for (int i = 0; i < 2; i++) {
            const int f = f0 + ty*2 + i;
            __half hi[4], lo[4];
#pragma unroll
            for (int j = 0; j < 4; j++) split_h(acc[i][j], hi[j], lo[j]);
            uint2 hv2, lv2;
            hv2.x = pk2h(hi[0], hi[1]); hv2.y = pk2h(hi[2], hi[3]);
            lv2.x = pk2h(lo[0], lo[1]); lv2.y = pk2h(lo[2], lo[3]);
            *(uint2*)&p.Mh[(size_t)f * 512 + e0 + tx*4] = hv2;
            *(uint2*)&p.Ml[(size_t)f * 512 + e0 + tx*4] = lv2;
        }
    } else if (blk < FP_NT0) {
        // ---- prep_wv: wv[r] = Y[r,:]·hv  (8 rows per block)
        float* hs = (float*)smbuf;     // 256 floats
        if (tid < 256) hs[tid] = p.hv[tid];
        __syncthreads();
        const int lane = tid & 31;
        const int w = tid >> 5;
        const size_t r = (size_t)(blk - FP_WV0) * 8 + w;
        const float* row = p.Y + r * 256;
        float s = 0.0f;
#pragma unroll
        for (int j = 0; j < 8; j++) s = fmaf(row[lane * 8 + j], hs[lane * 8 + j], s);
#pragma unroll
        for (int o = 16; o; o >>= 1) s += __shfl_xor_sync(0xffffffffu, s, o);
        if (lane == 0) p.wv[r] = s;
    } else if (blk < FP_OB0) {
        // ---- prep_NT: NT[e,f] = Wv[f,:]·Wo[:,e]  (64e x 32f tile)
        float (*Os)[65] = (float(*)[65])smbuf;                    // 64x65
        float (*Vs)[65] = (float(*)[65])(smbuf + 64*65*4);        // 32x65
        const int idx = blk - FP_NT0;
        const int f0 = (idx & 7) * 32, e0 = (idx >> 3) * 64;
        const int tx = tid & 15, ty = tid >> 4;

        float acc[4][2] = {};
        for (int a0 = 0; a0 < 512; a0 += 64) {
#pragma unroll
            for (int it = 0; it < 4; it++) {
                const int j = tid + it * 256;
                const int r = j >> 4, c4 = j & 15;
                const float4 v = *(const float4*)&p.Wo[(size_t)(a0 + r) * 512 + e0 + c4 * 4];
                Os[r][c4*4+0] = v.x; Os[r][c4*4+1] = v.y;
                Os[r][c4*4+2] = v.z; Os[r][c4*4+3] = v.w;
            }
#pragma unroll
            for (int it = 0; it < 2; it++) {
                const int j = tid + it * 256;
                const int r = j >> 4, c4 = j & 15;
                const float4 v = *(const float4*)&p.Wv[(size_t)(f0 + r) * 512 + a0 + c4 * 4];
                Vs[r][c4*4+0] = v.x; Vs[r][c4*4+1] = v.y;
                Vs[r][c4*4+2] = v.z; Vs[r][c4*4+3] = v.w;
            }
            __syncthreads();
#pragma unroll 8
            for (int a = 0; a < 64; a++) {
                float e4[4], fv0, fv1;
#pragma unroll
                for (int i = 0; i < 4; i++) e4[i] = Os[a][ty*4+i];
                fv0 = Vs[tx*2][a]; fv1 = Vs[tx*2+1][a];
#pragma unroll
                for (int i = 0; i < 4; i++) {
                    acc[i][0] = fmaf(e4[i], fv0, acc[i][0]);
                    acc[i][1] = fmaf(e4[i], fv1, acc[i][1]);
                }
            }
            __syncthreads();
        }
#pragma unroll
        for (int i = 0; i < 4; i++) {
            const int e = e0 + ty*4 + i;
            __half hi[2], lo[2];
#pragma unroll
            for (int j = 0; j < 2; j++) split_h(acc[i][j], hi[j], lo[j]);
            *(uint32_t*)&p.Nh[(size_t)e * 256 + f0 + tx*2] = pk2h(hi[0], hi[1]);
            *(uint32_t*)&p.Nl[(size_t)e * 256 + f0 + tx*2] = pk2h(lo[0], lo[1]);
        }
    } else {
        // ---- prep_ob: ob[e] = bo[e] + bv·Wo[:,e]  (256 thr x 2 e)
#pragma unroll
        for (int half = 0; half < 2; half++) {
            const int e = tid + half * 256;
            float s = p.bo[e];
            for (int a = 0; a < 512; a++)
                s = fmaf(p.bv[a], p.Wo[(size_t)a * 512 + e], s);
            p.ob[e] = s;
        }
    }
}

// ---------------------------------------------------------------------------
// Softmax over 2048-col fp32 rows -> hi/lo fp16 row-major
// ---------------------------------------------------------------------------
__global__ __launch_bounds__(256)
void softmax_split(const float* __restrict__ S, __half* __restrict__ Sh,
                   __half* __restrict__ Sl)
{
    const size_t r = blockIdx.x;
    const float* row = S + r * 2048;
    const int tid = threadIdx.x;
    const int c0 = tid * 8;

    float v[8];
    *(float4*)&v[0] = *(const float4*)&row[c0];
    *(float4*)&v[4] = *(const float4*)&row[c0 + 4];

    __shared__ float red[8];
    float m = v[0];
#pragma unroll
    for (int e = 1; e < 8; e++) m = fmaxf(m, v[e]);
#pragma unroll
    for (int o = 16; o; o >>= 1) m = fmaxf(m, __shfl_xor_sync(0xffffffffu, m, o));
    if ((tid & 31) == 0) red[tid >> 5] = m;
    __syncthreads();
    float mx = red[0];
#pragma unroll
    for (int i = 1; i < 8; i++) mx = fmaxf(mx, red[i]);
    __syncthreads();

    float s = 0.0f;
#pragma unroll
    for (int e = 0; e < 8; e++) { v[e] = __expf(v[e] - mx); s += v[e]; }
#pragma unroll
    for (int o = 16; o; o >>= 1) s += __shfl_xor_sync(0xffffffffu, s, o);
    if ((tid & 31) == 0) red[tid >> 5] = s;
    __syncthreads();
    float st = 0.0f;
#pragma unroll
    for (int i = 0; i < 8; i++) st += red[i];
    const float inv = 1.0f / st;

    __half hi[8], lo[8];
#pragma unroll
    for (int e = 0; e < 8; e++) split_h(v[e] * inv, hi[e], lo[e]);
    uint4 hv4, lv4;
    hv4.x = pk2h(hi[0],hi[1]); hv4.y = pk2h(hi[2],hi[3]);
    hv4.z = pk2h(hi[4],hi[5]); hv4.w = pk2h(hi[6],hi[7]);
    lv4.x = pk2h(lo[0],lo[1]); lv4.y = pk2h(lo[2],lo[3]);
    lv4.z = pk2h(lo[4],lo[5]); lv4.w = pk2h(lo[6],lo[7]);
    *(uint4*)&Sh[r * 2048 + c0] = hv4;
    *(uint4*)&Sl[r * 2048 + c0] = lv4;
}

// ---------------------------------------------------------------------------
// Launch
// ---------------------------------------------------------------------------
extern "C" void kernel_launch(void* const* d_in, const int* in_sizes, int n_in,
                              void* d_out, int out_size)
{
    const float* X  = (const float*)d_in[0];
    const float* Y  = (const float*)d_in[1];
    const float* Wq = (const float*)d_in[2];
    const float* bq = (const float*)d_in[3];
    const float* Wk = (const float*)d_in[4];
    const float* Wv = (const float*)d_in[6];
    const float* bv = (const float*)d_in[7];
    const float* Wo = (const float*)d_in[8];
    const float* bo = (const float*)d_in[9];
    float* out = (float*)d_out;

    constexpr int SMEM3 = STAGES * (2 * A_TILE_B + 2 * B_TILE_B);   // 184320
    constexpr int SMEM2 = STAGES * (2 * A_TILE_B + 1 * B_TILE_B);   // 122880
    cudaFuncSetAttribute(gemm_mma<3,0,1>, cudaFuncAttributeMaxDynamicSharedMemorySize, SMEM3);
    cudaFuncSetAttribute(gemm_mma<3,1,0>, cudaFuncAttributeMaxDynamicSharedMemorySize, SMEM3);
    cudaFuncSetAttribute(gemm_mma<2,1,0>, cudaFuncAttributeMaxDynamicSharedMemorySize, SMEM2);

    __half *Xh,*Xl,*Yh,*Yl,*YTh,*YTl,*Mh,*Ml,*Nh,*Nl,*Th,*Tl,*Ph,*Pl,*Ch,*Cl;
    float *S,*hv,*wv,*ob;
    cudaGetSymbolAddress((void**)&Xh, g_Xh);   cudaGetSymbolAddress((void**)&Xl, g_Xl);
    cudaGetSymbolAddress((void**)&Yh, g_Yh);   cudaGetSymbolAddress((void**)&Yl, g_Yl);
    cudaGetSymbolAddress((void**)&YTh, g_YTh); cudaGetSymbolAddress((void**)&YTl, g_YTl);
    cudaGetSymbolAddress((void**)&Mh, g_Mh);   cudaGetSymbolAddress((void**)&Ml, g_Ml);
    cudaGetSymbolAddress((void**)&Nh, g_Nh);   cudaGetSymbolAddress((void**)&Nl, g_Nl);
    cudaGetSymbolAddress((void**)&Th, g_Th);   cudaGetSymbolAddress((void**)&Tl, g_Tl);
    cudaGetSymbolAddress((void**)&Ph, g_Ph);   cudaGetSymbolAddress((void**)&Pl, g_Pl);
    cudaGetSymbolAddress((void**)&Ch, g_Ch);   cudaGetSymbolAddress((void**)&Cl, g_Cl);
    cudaGetSymbolAddress((void**)&S, g_S);
    cudaGetSymbolAddress((void**)&hv, g_hv);
    cudaGetSymbolAddress((void**)&wv, g_wv);
    cudaGetSymbolAddress((void**)&ob, g_ob);

    // 1: hv (feeds wv inside fused prep)
    prep_hv<<<1, 256>>>(Wk, bq, hv);
    // 2: fused prep (everything independent, one launch)
    {
        PrepArgs p{X, Y, Wq, Wk, Wv, Wo, bv, bo, hv,
                   Xh, Xl, Yh, Yl, YTh, YTl, Mh, Ml, Nh, Nl,
                   wv, ob};
        fused_prep<<<FP_NBLK, 256>>>(p);
    }
    // 3: T = X @ M -> split [16384,256]
    {
        GemmArgs a{Xh, Xl, Mh, Ml, nullptr, nullptr, Th, Tl,
                   512, 0, 0, 0, 256, 0};
        gemm_mma<3,1,0><<<dim3(1,128,1), 512, SMEM3>>>(a);
    }
    // 4: S = T_z @ Y_z^T + wv -> fp32 [1024,2048] x16
    {
        GemmArgs a{Th, Tl, Yh, Yl, wv, S, nullptr, nullptr,
                   256, (long long)1024*256, (long long)2048*256,
                   (long long)1024*2048, 2048, 2048};
        gemm_mma<3,0,1><<<dim3(8,8,16), 512, SMEM3>>>(a);
    }
    // 5: softmax -> P split
    softmax_split<<<16384, 256>>>(S, Ph, Pl);
    // 6: C = (Ph+Pl) @ Yh -> split [1024,256] x16  (2-term)
    {
        GemmArgs a{Ph, Pl, YTh, nullptr, nullptr, nullptr, Ch, Cl,
                   2048, (long long)1024*2048, (long long)256*2048,
                   (long long)1024*256, 256, 0};
        gemm_mma<2,1,0><<<dim3(1,8,16), 512, SMEM2>>>(a);
    }
    // 7: out = C @ N + ob -> fp32 [16384,512]  (3-term)
    {
        GemmArgs a{Ch, Cl, Nh, Nl, ob, out, nullptr, nullptr,
                   256, 0, 0, 0, 512, 0};
        gemm_mma<3,0,1><<<dim3(2,128,1), 512, SMEM3>>>(a);
    }
}